// round 5
// baseline (speedup 1.0000x reference)
#include <cuda_runtime.h>
#include <cuda_bf16.h>
#include <cstdint>

#define Bdim 2
#define Hdim 16
#define Sdim 2048
#define Ddim 128
#define BHdim (Bdim * Hdim)
#define NELEM 8388608   // BH * S * D

__device__ __nv_bfloat16 g_Qhi[NELEM];
__device__ __nv_bfloat16 g_Qlo[NELEM];
__device__ __nv_bfloat16 g_Khi[NELEM];
__device__ __nv_bfloat16 g_Klo[NELEM];
__device__ __nv_bfloat16 g_Vthi[NELEM];   // transposed: [bh][d][s]
__device__ __nv_bfloat16 g_Vtlo[NELEM];

// ------------------- helpers -------------------
__device__ __forceinline__ void mma_bf16(float& d0, float& d1, float& d2, float& d3,
                                         uint32_t a0, uint32_t a1, uint32_t a2, uint32_t a3,
                                         uint32_t b0, uint32_t b1) {
    asm volatile(
        "mma.sync.aligned.m16n8k16.row.col.f32.bf16.bf16.f32 "
        "{%0,%1,%2,%3}, {%4,%5,%6,%7}, {%8,%9}, {%0,%1,%2,%3};"
        : "+f"(d0), "+f"(d1), "+f"(d2), "+f"(d3)
        : "r"(a0), "r"(a1), "r"(a2), "r"(a3), "r"(b0), "r"(b1));
}
__device__ __forceinline__ void ldsm4(uint32_t& r0, uint32_t& r1, uint32_t& r2, uint32_t& r3,
                                      uint32_t addr) {
    asm volatile("ldmatrix.sync.aligned.m8n8.x4.shared.b16 {%0,%1,%2,%3}, [%4];"
                 : "=r"(r0), "=r"(r1), "=r"(r2), "=r"(r3) : "r"(addr));
}
__device__ __forceinline__ void split2(float a, float b, uint32_t& hi, uint32_t& lo) {
    __nv_bfloat16 ha = __float2bfloat16(a), hb = __float2bfloat16(b);
    float ra = a - __bfloat162float(ha);
    float rb = b - __bfloat162float(hb);
    __nv_bfloat162 hp; hp.x = ha; hp.y = hb;
    __nv_bfloat162 lp = __floats2bfloat162_rn(ra, rb);
    hi = *reinterpret_cast<uint32_t*>(&hp);
    lo = *reinterpret_cast<uint32_t*>(&lp);
}

// ------------------- convert kernels -------------------
__global__ __launch_bounds__(256)
void conv_qk_kernel(const float* __restrict__ Q, const float* __restrict__ K)
{
    const size_t n4 = (size_t)NELEM / 4;
    size_t i = (size_t)blockIdx.x * 256 + threadIdx.x;
    const float sc = 0.08838834764831843f;  // 1/sqrt(128)
    float4 v; __nv_bfloat16 *hip, *lop; size_t idx;
    if (i < n4) {
        idx = i;
        v = ((const float4*)Q)[idx];
        v.x *= sc; v.y *= sc; v.z *= sc; v.w *= sc;
        hip = g_Qhi; lop = g_Qlo;
    } else {
        idx = i - n4;
        v = ((const float4*)K)[idx];
        hip = g_Khi; lop = g_Klo;
    }
    uint32_t h0, h1, l0, l1;
    split2(v.x, v.y, h0, l0);
    split2(v.z, v.w, h1, l1);
    ((uint2*)hip)[idx] = make_uint2(h0, h1);
    ((uint2*)lop)[idx] = make_uint2(l0, l1);
}

__global__ __launch_bounds__(256)
void conv_v_kernel(const float* __restrict__ V)
{
    __shared__ float tile[32][33];
    const int bh = blockIdx.z;
    const int s0 = blockIdx.x * 32;
    const int d0 = blockIdx.y * 32;
    const int tx = threadIdx.x, ty = threadIdx.y;
    const float* Vh = V + (size_t)bh * Sdim * Ddim;

    for (int i = ty; i < 32; i += 8)
        tile[i][tx] = Vh[(size_t)(s0 + i) * Ddim + d0 + tx];
    __syncthreads();

    const size_t base = (size_t)bh * Ddim * Sdim;
    for (int i = ty; i < 32; i += 8) {
        float x = tile[tx][i];   // V[s0+tx][d0+i]
        __nv_bfloat16 hb = __float2bfloat16(x);
        float r = x - __bfloat162float(hb);
        size_t o = base + (size_t)(d0 + i) * Sdim + s0 + tx;
        g_Vthi[o] = hb;
        g_Vtlo[o] = __float2bfloat16(r);
    }
}

// ------------------- QK HMMA kernel (ldmatrix) -------------------
// CTA: 128x128, full K=128 resident. 8 warps 2(M)x4(N), warp 64x32.
#define LDA_QK 136
#define QK_PL  (128 * LDA_QK * 2)          // plane bytes: 34816
#define QK_SMEM (4 * QK_PL)                // 139264

__global__ __launch_bounds__(256, 1)
void qk_mma_kernel(float* __restrict__ W)
{
    extern __shared__ __nv_bfloat16 sm[];
    const int tid = threadIdx.x;
    const int bh = blockIdx.z;
    const int q0 = blockIdx.y * 128;
    const int k0 = blockIdx.x * 128;

    const size_t qbase = (size_t)bh * Sdim * Ddim + (size_t)q0 * Ddim;
    const size_t kbase = (size_t)bh * Sdim * Ddim + (size_t)k0 * Ddim;

    __nv_bfloat16* sQhi = sm;
    __nv_bfloat16* sQlo = sm + 128 * LDA_QK;
    __nv_bfloat16* sKhi = sm + 2 * 128 * LDA_QK;
    __nv_bfloat16* sKlo = sm + 3 * 128 * LDA_QK;

#pragma unroll
    for (int j = 0; j < 8; j++) {
        int f = j * 256 + tid;
        int row = f >> 4, c8 = (f & 15) * 8;
        size_t g = (size_t)row * Ddim + c8;
        int s = row * LDA_QK + c8;
        *(uint4*)&sQhi[s] = *(const uint4*)(g_Qhi + qbase + g);
        *(uint4*)&sQlo[s] = *(const uint4*)(g_Qlo + qbase + g);
        *(uint4*)&sKhi[s] = *(const uint4*)(g_Khi + kbase + g);
        *(uint4*)&sKlo[s] = *(const uint4*)(g_Klo + kbase + g);
    }
    __syncthreads();

    const int lane = tid & 31, wid = tid >> 5;
    const int wm = (wid >> 2) * 64, wn = (wid & 3) * 32;
    const int ar = lane >> 2, ac = (lane & 3) * 2;

    const uint32_t smb = (uint32_t)__cvta_generic_to_shared(sm);
    // ldmatrix per-thread source rows/cols
    const int a_row = wm + ((lane >> 3) & 1) * 8 + (lane & 7);
    const int a_col = (lane >> 4) * 8;
    const int b_row = wn + (lane >> 4) * 8 + (lane & 7);
    const int b_col = ((lane >> 3) & 1) * 8;

    float acc[4][4][4];
#pragma unroll
    for (int mi = 0; mi < 4; mi++)
#pragma unroll
        for (int ni = 0; ni < 4; ni++)
#pragma unroll
            for (int r = 0; r < 4; r++) acc[mi][ni][r] = 0.f;

#pragma unroll
    for (int ks = 0; ks < 8; ks++) {
        const int kb = ks * 16;
        uint32_t ah[4][4], al[4][4], bh[4][2], bl[4][2];
#pragma unroll
        for (int mi = 0; mi < 4; mi++) {
            uint32_t a = smb + (uint32_t)(((a_row + mi * 16) * LDA_QK + kb + a_col) << 1);
            ldsm4(ah[mi][0], ah[mi][1], ah[mi][2], ah[mi][3], a);
            ldsm4(al[mi][0], al[mi][1], al[mi][2], al[mi][3], a + QK_PL);
        }
#pragma unroll
        for (int np = 0; np < 2; np++) {
            uint32_t b = smb + 2 * QK_PL + (uint32_t)(((b_row + np * 16) * LDA_QK + kb + b_col) << 1);
            uint32_t x0, x1, x2, x3;
            ldsm4(x0, x1, x2, x3, b);
            bh[np * 2][0] = x0; bh[np * 2][1] = x1; bh[np * 2 + 1][0] = x2; bh[np * 2 + 1][1] = x3;
            ldsm4(x0, x1, x2, x3, b + QK_PL);
            bl[np * 2][0] = x0; bl[np * 2][1] = x1; bl[np * 2 + 1][0] = x2; bl[np * 2 + 1][1] = x3;
        }
#pragma unroll
        for (int mi = 0; mi < 4; mi++)
#pragma unroll
            for (int ni = 0; ni < 4; ni++) {
                float* c = acc[mi][ni];
                mma_bf16(c[0], c[1], c[2], c[3], ah[mi][0], ah[mi][1], ah[mi][2], ah[mi][3], bh[ni][0], bh[ni][1]);
                mma_bf16(c[0], c[1], c[2], c[3], ah[mi][0], ah[mi][1], ah[mi][2], ah[mi][3], bl[ni][0], bl[ni][1]);
                mma_bf16(c[0], c[1], c[2], c[3], al[mi][0], al[mi][1], al[mi][2], al[mi][3], bh[ni][0], bh[ni][1]);
            }
    }

    float* Wh = W + (size_t)bh * Sdim * Sdim;
#pragma unroll
    for (int mi = 0; mi < 4; mi++) {
        const int r = q0 + wm + mi * 16 + ar;
#pragma unroll
        for (int ni = 0; ni < 4; ni++) {
            const int cc = k0 + wn + ni * 8 + ac;
            float* c = acc[mi][ni];
            *(float2*)&Wh[(size_t)r * Sdim + cc]       = make_float2(c[0], c[1]);
            *(float2*)&Wh[(size_t)(r + 8) * Sdim + cc] = make_float2(c[2], c[3]);
        }
    }
}

// ------------------- softmax -------------------
__global__ __launch_bounds__(256)
void softmax_kernel(float* __restrict__ W)
{
    float* p = W + (size_t)blockIdx.x * Sdim;
    const int tid = threadIdx.x, lane = tid & 31, warp = tid >> 5;

    float4 v0 = *(const float4*)(p + tid * 8);
    float4 v1 = *(const float4*)(p + tid * 8 + 4);
    float x[8] = {v0.x, v0.y, v0.z, v0.w, v1.x, v1.y, v1.z, v1.w};

    __shared__ float smax[8], ssum[8];

    float m = x[0];
#pragma unroll
    for (int j = 1; j < 8; j++) m = fmaxf(m, x[j]);
#pragma unroll
    for (int o = 16; o > 0; o >>= 1) m = fmaxf(m, __shfl_xor_sync(0xffffffffu, m, o));
    if (lane == 0) smax[warp] = m;
    __syncthreads();
    float bm = smax[0];
#pragma unroll
    for (int w = 1; w < 8; w++) bm = fmaxf(bm, smax[w]);

    float s = 0.f;
#pragma unroll
    for (int j = 0; j < 8; j++) { x[j] = __expf(x[j] - bm); s += x[j]; }
#pragma unroll
    for (int o = 16; o > 0; o >>= 1) s += __shfl_xor_sync(0xffffffffu, s, o);
    if (lane == 0) ssum[warp] = s;
    __syncthreads();
    float bs = 0.f;
#pragma unroll
    for (int w = 0; w < 8; w++) bs += ssum[w];

    const float inv = 1.f / bs;
#pragma unroll
    for (int j = 0; j < 8; j++) x[j] *= inv;
    *(float4*)(p + tid * 8)     = make_float4(x[0], x[1], x[2], x[3]);
    *(float4*)(p + tid * 8 + 4) = make_float4(x[4], x[5], x[6], x[7]);
}

// ------------------- PV HMMA kernel (ldmatrix, 2-stage) -------------------
// CTA: 128x128, K=2048 in 64 chunks of 32; double-buffered smem, 1 sync/iter.
#define LDB_PV 40
#define PV_PL   (128 * LDB_PV * 2)          // plane bytes: 10240
#define PV_STG  (4 * PV_PL)                 // stage bytes: 40960
#define PV_SMEM (2 * PV_STG)                // 81920

__global__ __launch_bounds__(256, 1)
void pv_mma_kernel(const float* __restrict__ W, float* __restrict__ O)
{
    extern __shared__ __nv_bfloat16 sm[];
    const int tid = threadIdx.x;
    const int q0 = blockIdx.x * 128;
    const int bh = blockIdx.y;

    const int row = tid >> 1, hf = tid & 1;
    const float* Wp = W + (size_t)bh * Sdim * Sdim + (size_t)(q0 + row) * Sdim + hf * 16;
    const __nv_bfloat16* Vhp = g_Vthi + (size_t)bh * Ddim * Sdim + (size_t)row * Sdim + hf * 16;
    const __nv_bfloat16* Vlp = g_Vtlo + (size_t)bh * Ddim * Sdim + (size_t)row * Sdim + hf * 16;

    const int lane = tid & 31, wid = tid >> 5;
    const int wm = (wid >> 2) * 64, wn = (wid & 3) * 32;
    const int ar = lane >> 2, ac = (lane & 3) * 2;

    const uint32_t smb = (uint32_t)__cvta_generic_to_shared(sm);
    const int a_row = wm + ((lane >> 3) & 1) * 8 + (lane & 7);
    const int a_col = (lane >> 4) * 8;
    const int b_row = wn + (lane >> 4) * 8 + (lane & 7);
    const int b_col = ((lane >> 3) & 1) * 8;

    float acc[4][4][4];
#pragma unroll
    for (int mi = 0; mi < 4; mi++)
#pragma unroll
        for (int ni = 0; ni < 4; ni++)
#pragma unroll
            for (int r = 0; r < 4; r++) acc[mi][ni][r] = 0.f;

    float4 fa[4];
    uint4 vh[2], vl[2];
    // prefetch chunk 0 (W read-once -> streaming loads)
#pragma unroll
    for (int g = 0; g < 4; g++) fa[g] = __ldcs((const float4*)Wp + g);
#pragma unroll
    for (int u = 0; u < 2; u++) { vh[u] = *(const uint4*)(Vhp + u * 8); vl[u] = *(const uint4*)(Vlp + u * 8); }

    const int sbase = row * LDB_PV + hf * 16;

    for (int c = 0; c < 64; c++) {
        const uint32_t stB = (uint32_t)(c & 1) * PV_STG;   // stage byte offset
        __nv_bfloat16* stg = sm + (c & 1) * (PV_STG / 2);

        // store staged regs -> smem (split W to hi/lo)
        {
            __nv_bfloat16* sPhi = stg;
            __nv_bfloat16* sPlo = stg + 128 * LDB_PV;
            __nv_bfloat16* sVhi = stg + 2 * 128 * LDB_PV;
            __nv_bfloat16* sVlo = stg + 3 * 128 * LDB_PV;
#pragma unroll
            for (int g = 0; g < 4; g++) {
                uint32_t h0, h1, l0, l1;
                split2(fa[g].x, fa[g].y, h0, l0);
                split2(fa[g].z, fa[g].w, h1, l1);
                *(uint2*)&sPhi[sbase + g * 4] = make_uint2(h0, h1);
                *(uint2*)&sPlo[sbase + g * 4] = make_uint2(l0, l1);
            }
#pragma unroll
            for (int u = 0; u < 2; u++) {
                *(uint4*)&sVhi[sbase + u * 8] = vh[u];
                *(uint4*)&sVlo[sbase + u * 8] = vl[u];
            }
        }
        __syncthreads();

        // prefetch next chunk
        if (c < 63) {
            const int off = (c + 1) * 32;
#pragma unroll
            for (int g = 0; g < 4; g++) fa[g] = __ldcs((const float4*)(Wp + off) + g);
#pragma unroll
            for (int u = 0; u < 2; u++) {
                vh[u] = *(const uint4*)(Vhp + off + u * 8);
                vl[u] = *(const uint4*)(Vlp + off + u * 8);
            }
        }

        // compute on current stage
#pragma unroll
        for (int ks = 0; ks < 2; ks++) {
            const int kb = ks * 16;
            uint32_t ah[4][4], al[4][4], bh[4][2], bl[4][2];
#pragma unroll
            for (int mi = 0; mi < 4; mi++) {
                uint32_t a = smb + stB + (uint32_t)(((a_row + mi * 16) * LDB_PV + kb + a_col) << 1);
                ldsm4(ah[mi][0], ah[mi][1], ah[mi][2], ah[mi][3], a);
                ldsm4(al[mi][0], al[mi][1], al[mi][2], al[mi][3], a + PV_PL);
            }
#pragma unroll
            for (int np = 0; np < 2; np++) {
                uint32_t b = smb + stB + 2 * PV_PL + (uint32_t)(((b_row + np * 16) * LDB_PV + kb + b_col) << 1);
                uint32_t x0, x1, x2, x3;
                ldsm4(x0, x1, x2, x3, b);
                bh[np * 2][0] = x0; bh[np * 2][1] = x1; bh[np * 2 + 1][0] = x2; bh[np * 2 + 1][1] = x3;
                ldsm4(x0, x1, x2, x3, b + PV_PL);
                bl[np * 2][0] = x0; bl[np * 2][1] = x1; bl[np * 2 + 1][0] = x2; bl[np * 2 + 1][1] = x3;
            }
#pragma unroll
            for (int mi = 0; mi < 4; mi++)
#pragma unroll
                for (int ni = 0; ni < 4; ni++) {
                    float* cc = acc[mi][ni];
                    mma_bf16(cc[0], cc[1], cc[2], cc[3], ah[mi][0], ah[mi][1], ah[mi][2], ah[mi][3], bh[ni][0], bh[ni][1]);
                    mma_bf16(cc[0], cc[1], cc[2], cc[3], ah[mi][0], ah[mi][1], ah[mi][2], ah[mi][3], bl[ni][0], bl[ni][1]);
                    mma_bf16(cc[0], cc[1], cc[2], cc[3], al[mi][0], al[mi][1], al[mi][2], al[mi][3], bh[ni][0], bh[ni][1]);
                }
        }
    }

    float* Oh = O + (size_t)bh * Sdim * Ddim;
#pragma unroll
    for (int mi = 0; mi < 4; mi++) {
        const int r = q0 + wm + mi * 16 + ar;
#pragma unroll
        for (int ni = 0; ni < 4; ni++) {
            const int cc = wn + ni * 8 + ac;
            float* c = acc[mi][ni];
            *(float2*)&Oh[(size_t)r * Ddim + cc]       = make_float2(c[0], c[1]);
            *(float2*)&Oh[(size_t)(r + 8) * Ddim + cc] = make_float2(c[2], c[3]);
        }
    }
}

// ------------------- launch -------------------
extern "C" void kernel_launch(void* const* d_in, const int* in_sizes, int n_in,
                              void* d_out, int out_size)
{
    const float* Q = (const float*)d_in[0];
    const float* K = (const float*)d_in[1];
    const float* V = (const float*)d_in[2];
    float* out = (float*)d_out;
    float* Wt  = out + (size_t)NELEM;  // weights region

    cudaFuncSetAttribute(qk_mma_kernel, cudaFuncAttributeMaxDynamicSharedMemorySize, QK_SMEM);
    cudaFuncSetAttribute(pv_mma_kernel, cudaFuncAttributeMaxDynamicSharedMemorySize, PV_SMEM);

    conv_qk_kernel<<<2 * (NELEM / 4) / 256, 256>>>(Q, K);
    conv_v_kernel<<<dim3(Sdim / 32, Ddim / 32, BHdim), dim3(32, 8)>>>(V);

    qk_mma_kernel<<<dim3(Sdim / 128, Sdim / 128, BHdim), 256, QK_SMEM>>>(Wt);

    softmax_kernel<<<dim3(BHdim * Sdim), 256>>>(Wt);

    pv_mma_kernel<<<dim3(Sdim / 128, BHdim), 256, PV_SMEM>>>(Wt, out);
}

// round 6
// speedup vs baseline: 1.0066x; 1.0066x over previous
#include <cuda_runtime.h>
#include <cuda_bf16.h>
#include <cstdint>

#define Bdim 2
#define Hdim 16
#define Sdim 2048
#define Ddim 128
#define BHdim (Bdim * Hdim)
#define NELEM 8388608   // BH * S * D

__device__ __nv_bfloat16 g_Qhi[NELEM];
__device__ __nv_bfloat16 g_Qlo[NELEM];
__device__ __nv_bfloat16 g_Khi[NELEM];
__device__ __nv_bfloat16 g_Klo[NELEM];
__device__ __nv_bfloat16 g_Vthi[NELEM];   // transposed: [bh][d][s]
__device__ __nv_bfloat16 g_Vtlo[NELEM];
__device__ float2 g_tileStats[BHdim * Sdim * 16];  // per (row, ktile): (max, expsum)
__device__ float2 g_rowStats[BHdim * Sdim];        // per row: (max, 1/sum)

// ------------------- helpers -------------------
__device__ __forceinline__ void mma_bf16(float& d0, float& d1, float& d2, float& d3,
                                         uint32_t a0, uint32_t a1, uint32_t a2, uint32_t a3,
                                         uint32_t b0, uint32_t b1) {
    asm volatile(
        "mma.sync.aligned.m16n8k16.row.col.f32.bf16.bf16.f32 "
        "{%0,%1,%2,%3}, {%4,%5,%6,%7}, {%8,%9}, {%0,%1,%2,%3};"
        : "+f"(d0), "+f"(d1), "+f"(d2), "+f"(d3)
        : "r"(a0), "r"(a1), "r"(a2), "r"(a3), "r"(b0), "r"(b1));
}
__device__ __forceinline__ void ldsm4(uint32_t& r0, uint32_t& r1, uint32_t& r2, uint32_t& r3,
                                      uint32_t addr) {
    asm volatile("ldmatrix.sync.aligned.m8n8.x4.shared.b16 {%0,%1,%2,%3}, [%4];"
                 : "=r"(r0), "=r"(r1), "=r"(r2), "=r"(r3) : "r"(addr));
}
__device__ __forceinline__ void cpasync16(uint32_t dst, const void* src) {
    asm volatile("cp.async.cg.shared.global [%0], [%1], 16;" :: "r"(dst), "l"(src) : "memory");
}
__device__ __forceinline__ void split2(float a, float b, uint32_t& hi, uint32_t& lo) {
    __nv_bfloat16 ha = __float2bfloat16(a), hb = __float2bfloat16(b);
    float ra = a - __bfloat162float(ha);
    float rb = b - __bfloat162float(hb);
    __nv_bfloat162 hp; hp.x = ha; hp.y = hb;
    __nv_bfloat162 lp = __floats2bfloat162_rn(ra, rb);
    hi = *reinterpret_cast<uint32_t*>(&hp);
    lo = *reinterpret_cast<uint32_t*>(&lp);
}

// ------------------- convert kernels -------------------
__global__ __launch_bounds__(256)
void conv_qk_kernel(const float* __restrict__ Q, const float* __restrict__ K)
{
    const size_t n4 = (size_t)NELEM / 4;
    size_t i = (size_t)blockIdx.x * 256 + threadIdx.x;
    const float sc = 0.08838834764831843f;  // 1/sqrt(128)
    float4 v; __nv_bfloat16 *hip, *lop; size_t idx;
    if (i < n4) {
        idx = i;
        v = ((const float4*)Q)[idx];
        v.x *= sc; v.y *= sc; v.z *= sc; v.w *= sc;
        hip = g_Qhi; lop = g_Qlo;
    } else {
        idx = i - n4;
        v = ((const float4*)K)[idx];
        hip = g_Khi; lop = g_Klo;
    }
    uint32_t h0, h1, l0, l1;
    split2(v.x, v.y, h0, l0);
    split2(v.z, v.w, h1, l1);
    ((uint2*)hip)[idx] = make_uint2(h0, h1);
    ((uint2*)lop)[idx] = make_uint2(l0, l1);
}

__global__ __launch_bounds__(256)
void conv_v_kernel(const float* __restrict__ V)
{
    __shared__ float tile[32][33];
    const int bh = blockIdx.z;
    const int s0 = blockIdx.x * 32;
    const int d0 = blockIdx.y * 32;
    const int tx = threadIdx.x, ty = threadIdx.y;
    const float* Vh = V + (size_t)bh * Sdim * Ddim;

    for (int i = ty; i < 32; i += 8)
        tile[i][tx] = Vh[(size_t)(s0 + i) * Ddim + d0 + tx];
    __syncthreads();

    const size_t base = (size_t)bh * Ddim * Sdim;
    for (int i = ty; i < 32; i += 8) {
        float x = tile[tx][i];   // V[s0+tx][d0+i]
        __nv_bfloat16 hb = __float2bfloat16(x);
        float r = x - __bfloat162float(hb);
        size_t o = base + (size_t)(d0 + i) * Sdim + s0 + tx;
        g_Vthi[o] = hb;
        g_Vtlo[o] = __float2bfloat16(r);
    }
}

// ------------------- QK HMMA kernel (cp.async + stats epilogue) -------------------
#define LDA_QK 136
#define QK_PL  (128 * LDA_QK * 2)          // plane bytes: 34816
#define QK_SMEM (4 * QK_PL)                // 139264

__global__ __launch_bounds__(256, 1)
void qk_mma_kernel(float* __restrict__ W)
{
    extern __shared__ __nv_bfloat16 sm[];
    const int tid = threadIdx.x;
    const int bh = blockIdx.z;
    const int q0 = blockIdx.y * 128;
    const int k0 = blockIdx.x * 128;
    const int ktile = blockIdx.x;

    const size_t qbase = (size_t)bh * Sdim * Ddim + (size_t)q0 * Ddim;
    const size_t kbase = (size_t)bh * Sdim * Ddim + (size_t)k0 * Ddim;
    const uint32_t smb = (uint32_t)__cvta_generic_to_shared(sm);

    const __nv_bfloat16* gsrc0 = g_Qhi + qbase;
    const __nv_bfloat16* gsrc1 = g_Qlo + qbase;
    const __nv_bfloat16* gsrc2 = g_Khi + kbase;
    const __nv_bfloat16* gsrc3 = g_Klo + kbase;

    // two chunk groups (depth cols 0-63, 64-127), each a commit group
#pragma unroll
    for (int ch = 0; ch < 2; ch++) {
#pragma unroll
        for (int j = 0; j < 4; j++) {
            int idx = j * 256 + tid;
            int row = idx >> 3, g = idx & 7;
            uint32_t doff = (uint32_t)((row * LDA_QK + ch * 64 + g * 8) << 1);
            size_t goff = (size_t)row * Ddim + ch * 64 + g * 8;
            cpasync16(smb + 0 * QK_PL + doff, gsrc0 + goff);
            cpasync16(smb + 1 * QK_PL + doff, gsrc1 + goff);
            cpasync16(smb + 2 * QK_PL + doff, gsrc2 + goff);
            cpasync16(smb + 3 * QK_PL + doff, gsrc3 + goff);
        }
        asm volatile("cp.async.commit_group;" ::: "memory");
    }

    const int lane = tid & 31, wid = tid >> 5;
    const int wm = (wid >> 2) * 64, wn = (wid & 3) * 32;
    const int ar = lane >> 2, ac = (lane & 3) * 2;
    const int a_row = wm + ((lane >> 3) & 1) * 8 + (lane & 7);
    const int a_col = (lane >> 4) * 8;
    const int b_row = wn + (lane >> 4) * 8 + (lane & 7);
    const int b_col = ((lane >> 3) & 1) * 8;

    float acc[4][4][4];
#pragma unroll
    for (int mi = 0; mi < 4; mi++)
#pragma unroll
        for (int ni = 0; ni < 4; ni++)
#pragma unroll
            for (int r = 0; r < 4; r++) acc[mi][ni][r] = 0.f;

    asm volatile("cp.async.wait_group 1;" ::: "memory");
    __syncthreads();

#pragma unroll
    for (int ks = 0; ks < 8; ks++) {
        if (ks == 4) {
            asm volatile("cp.async.wait_group 0;" ::: "memory");
            __syncthreads();
        }
        const int kb = ks * 16;
        uint32_t ah[4][4], al[4][4], bh[4][2], bl[4][2];
#pragma unroll
        for (int mi = 0; mi < 4; mi++) {
            uint32_t a = smb + (uint32_t)(((a_row + mi * 16) * LDA_QK + kb + a_col) << 1);
            ldsm4(ah[mi][0], ah[mi][1], ah[mi][2], ah[mi][3], a);
            ldsm4(al[mi][0], al[mi][1], al[mi][2], al[mi][3], a + QK_PL);
        }
#pragma unroll
        for (int np = 0; np < 2; np++) {
            uint32_t b = smb + 2 * QK_PL + (uint32_t)(((b_row + np * 16) * LDA_QK + kb + b_col) << 1);
            uint32_t x0, x1, x2, x3;
            ldsm4(x0, x1, x2, x3, b);
            bh[np * 2][0] = x0; bh[np * 2][1] = x1; bh[np * 2 + 1][0] = x2; bh[np * 2 + 1][1] = x3;
            ldsm4(x0, x1, x2, x3, b + QK_PL);
            bl[np * 2][0] = x0; bl[np * 2][1] = x1; bl[np * 2 + 1][0] = x2; bl[np * 2 + 1][1] = x3;
        }
#pragma unroll
        for (int mi = 0; mi < 4; mi++)
#pragma unroll
            for (int ni = 0; ni < 4; ni++) {
                float* c = acc[mi][ni];
                mma_bf16(c[0], c[1], c[2], c[3], ah[mi][0], ah[mi][1], ah[mi][2], ah[mi][3], bh[ni][0], bh[ni][1]);
                mma_bf16(c[0], c[1], c[2], c[3], ah[mi][0], ah[mi][1], ah[mi][2], ah[mi][3], bl[ni][0], bl[ni][1]);
                mma_bf16(c[0], c[1], c[2], c[3], al[mi][0], al[mi][1], al[mi][2], al[mi][3], bh[ni][0], bh[ni][1]);
            }
    }

    // ---- stats epilogue: per-row (max, expsum) over this 128-col tile ----
    __syncthreads();   // smem tile data no longer needed
    float* sMax = (float*)sm;          // [4][128]
    float* sSum = (float*)sm + 512;    // [4][128]
    const int nw = wid & 3;

#pragma unroll
    for (int mi = 0; mi < 4; mi++)
#pragma unroll
        for (int hh = 0; hh < 2; hh++) {
            float v = acc[mi][0][2 * hh];
#pragma unroll
            for (int ni = 0; ni < 4; ni++) {
                v = fmaxf(v, acc[mi][ni][2 * hh]);
                v = fmaxf(v, acc[mi][ni][2 * hh + 1]);
            }
            v = fmaxf(v, __shfl_xor_sync(0xffffffffu, v, 1));
            v = fmaxf(v, __shfl_xor_sync(0xffffffffu, v, 2));
            if ((lane & 3) == 0)
                sMax[nw * 128 + wm + mi * 16 + hh * 8 + ar] = v;
        }
    __syncthreads();
    if (tid < 128) {
        float m = fmaxf(fmaxf(sMax[tid], sMax[128 + tid]),
                        fmaxf(sMax[256 + tid], sMax[384 + tid]));
        sMax[tid] = m;   // each tid touches only its own row slot
    }
    __syncthreads();
#pragma unroll
    for (int mi = 0; mi < 4; mi++)
#pragma unroll
        for (int hh = 0; hh < 2; hh++) {
            float mrow = sMax[wm + mi * 16 + hh * 8 + ar];
            float s = 0.f;
#pragma unroll
            for (int ni = 0; ni < 4; ni++)
                s += __expf(acc[mi][ni][2 * hh] - mrow) + __expf(acc[mi][ni][2 * hh + 1] - mrow);
            s += __shfl_xor_sync(0xffffffffu, s, 1);
            s += __shfl_xor_sync(0xffffffffu, s, 2);
            if ((lane & 3) == 0)
                sSum[nw * 128 + wm + mi * 16 + hh * 8 + ar] = s;
        }
    __syncthreads();
    if (tid < 128) {
        float S = sSum[tid] + sSum[128 + tid] + sSum[256 + tid] + sSum[384 + tid];
        g_tileStats[(size_t)(bh * Sdim + q0 + tid) * 16 + ktile] = make_float2(sMax[tid], S);
    }

    // ---- raw score stores ----
    float* Wh = W + (size_t)bh * Sdim * Sdim;
#pragma unroll
    for (int mi = 0; mi < 4; mi++) {
        const int r = q0 + wm + mi * 16 + ar;
#pragma unroll
        for (int ni = 0; ni < 4; ni++) {
            const int cc = k0 + wn + ni * 8 + ac;
            float* c = acc[mi][ni];
            *(float2*)&Wh[(size_t)r * Sdim + cc]       = make_float2(c[0], c[1]);
            *(float2*)&Wh[(size_t)(r + 8) * Sdim + cc] = make_float2(c[2], c[3]);
        }
    }
}

// ------------------- stats reduce: 16 tiles -> row (max, 1/sum) -------------------
__global__ __launch_bounds__(256)
void reduce_stats_kernel()
{
    const int row = blockIdx.x * 256 + threadIdx.x;
    float2 t[16];
    float m = -3.4e38f;
#pragma unroll
    for (int j = 0; j < 16; j++) {
        t[j] = g_tileStats[(size_t)row * 16 + j];
        m = fmaxf(m, t[j].x);
    }
    float S = 0.f;
#pragma unroll
    for (int j = 0; j < 16; j++) S += t[j].y * __expf(t[j].x - m);
    g_rowStats[row] = make_float2(m, 1.f / S);
}

// ------------------- PV HMMA kernel (fused softmax apply + normalized W write) ----
#define LDB_PV 40
#define PV_PL   (128 * LDB_PV * 2)          // plane bytes: 10240
#define PV_STG  (4 * PV_PL)                 // stage bytes: 40960
#define PV_SMEM (2 * PV_STG)                // 81920

__global__ __launch_bounds__(256, 1)
void pv_mma_kernel(float* __restrict__ W, float* __restrict__ O)
{
    extern __shared__ __nv_bfloat16 sm[];
    const int tid = threadIdx.x;
    const int q0 = blockIdx.x * 128;
    const int bh = blockIdx.y;

    const int row = tid >> 1, hf = tid & 1;
    float* Wq = W + (size_t)bh * Sdim * Sdim + (size_t)(q0 + row) * Sdim + hf * 16;
    const __nv_bfloat16* Vhp = g_Vthi + (size_t)bh * Ddim * Sdim + (size_t)row * Sdim + hf * 16;
    const __nv_bfloat16* Vlp = g_Vtlo + (size_t)bh * Ddim * Sdim + (size_t)row * Sdim + hf * 16;

    const float2 st = g_rowStats[bh * Sdim + q0 + row];
    const float rm = st.x, rinv = st.y;

    const int lane = tid & 31, wid = tid >> 5;
    const int wm = (wid >> 2) * 64, wn = (wid & 3) * 32;
    const int ar = lane >> 2, ac = (lane & 3) * 2;

    const uint32_t smb = (uint32_t)__cvta_generic_to_shared(sm);
    const int a_row = wm + ((lane >> 3) & 1) * 8 + (lane & 7);
    const int a_col = (lane >> 4) * 8;
    const int b_row = wn + (lane >> 4) * 8 + (lane & 7);
    const int b_col = ((lane >> 3) & 1) * 8;

    float acc[4][4][4];
#pragma unroll
    for (int mi = 0; mi < 4; mi++)
#pragma unroll
        for (int ni = 0; ni < 4; ni++)
#pragma unroll
            for (int r = 0; r < 4; r++) acc[mi][ni][r] = 0.f;

    float4 fa[4];
    uint4 vh[2], vl[2];
#pragma unroll
    for (int g = 0; g < 4; g++) fa[g] = __ldcs((const float4*)Wq + g);
#pragma unroll
    for (int u = 0; u < 2; u++) { vh[u] = *(const uint4*)(Vhp + u * 8); vl[u] = *(const uint4*)(Vlp + u * 8); }

    const int sbase = row * LDB_PV + hf * 16;

    for (int c = 0; c < 64; c++) {
        const uint32_t stB = (uint32_t)(c & 1) * PV_STG;
        __nv_bfloat16* stg = sm + (c & 1) * (PV_STG / 2);

        // exp-normalize, write normalized W, split to hi/lo smem planes
        {
            __nv_bfloat16* sPhi = stg;
            __nv_bfloat16* sPlo = stg + 128 * LDB_PV;
            __nv_bfloat16* sVhi = stg + 2 * 128 * LDB_PV;
            __nv_bfloat16* sVlo = stg + 3 * 128 * LDB_PV;
#pragma unroll
            for (int g = 0; g < 4; g++) {
                float4 w4 = fa[g];
                float4 p4 = make_float4(__expf(w4.x - rm) * rinv, __expf(w4.y - rm) * rinv,
                                        __expf(w4.z - rm) * rinv, __expf(w4.w - rm) * rinv);
                __stcs((float4*)(Wq + c * 32) + g, p4);
                uint32_t h0, h1, l0, l1;
                split2(p4.x, p4.y, h0, l0);
                split2(p4.z, p4.w, h1, l1);
                *(uint2*)&sPhi[sbase + g * 4] = make_uint2(h0, h1);
                *(uint2*)&sPlo[sbase + g * 4] = make_uint2(l0, l1);
            }
#pragma unroll
            for (int u = 0; u < 2; u++) {
                *(uint4*)&sVhi[sbase + u * 8] = vh[u];
                *(uint4*)&sVlo[sbase + u * 8] = vl[u];
            }
        }
        __syncthreads();

        if (c < 63) {
            const int off = (c + 1) * 32;
#pragma unroll
            for (int g = 0; g < 4; g++) fa[g] = __ldcs((const float4*)(Wq + off) + g);
#pragma unroll
            for (int u = 0; u < 2; u++) {
                vh[u] = *(const uint4*)(Vhp + off + u * 8);
                vl[u] = *(const uint4*)(Vlp + off + u * 8);
            }
        }

#pragma unroll
        for (int ks = 0; ks < 2; ks++) {
            const int kb = ks * 16;
            uint32_t ah[4][4], al[4][4], bh[4][2], bl[4][2];
#pragma unroll
            for (int mi = 0; mi < 4; mi++) {
                uint32_t a = smb + stB + (uint32_t)(((a_row + mi * 16) * LDB_PV + kb + a_col) << 1);
                ldsm4(ah[mi][0], ah[mi][1], ah[mi][2], ah[mi][3], a);
                ldsm4(al[mi][0], al[mi][1], al[mi][2], al[mi][3], a + PV_PL);
            }
#pragma unroll
            for (int np = 0; np < 2; np++) {
                uint32_t b = smb + stB + 2 * PV_PL + (uint32_t)(((b_row + np * 16) * LDB_PV + kb + b_col) << 1);
                uint32_t x0, x1, x2, x3;
                ldsm4(x0, x1, x2, x3, b);
                bh[np * 2][0] = x0; bh[np * 2][1] = x1; bh[np * 2 + 1][0] = x2; bh[np * 2 + 1][1] = x3;
                ldsm4(x0, x1, x2, x3, b + PV_PL);
                bl[np * 2][0] = x0; bl[np * 2][1] = x1; bl[np * 2 + 1][0] = x2; bl[np * 2 + 1][1] = x3;
            }
#pragma unroll
            for (int mi = 0; mi < 4; mi++)
#pragma unroll
                for (int ni = 0; ni < 4; ni++) {
                    float* cc = acc[mi][ni];
                    mma_bf16(cc[0], cc[1], cc[2], cc[3], ah[mi][0], ah[mi][1], ah[mi][2], ah[mi][3], bh[ni][0], bh[ni][1]);
                    mma_bf16(cc[0], cc[1], cc[2], cc[3], ah[mi][0], ah[mi][1], ah[mi][2], ah[mi][3], bl[ni][0], bl[ni][1]);
                    mma_bf16(cc[0], cc[1], cc[2], cc[3], al[mi][0], al[mi][1], al[mi][2], al[mi][3], bh[ni][0], bh[ni][1]);
                }
        }
    }

    float* Oh = O + (size_t)bh * Sdim * Ddim;
#pragma unroll
    for (int mi = 0; mi < 4; mi++) {
        const int r = q0 + wm + mi * 16 + ar;
#pragma unroll
        for (int ni = 0; ni < 4; ni++) {
            const int cc = wn + ni * 8 + ac;
            float* c = acc[mi][ni];
            *(float2*)&Oh[(size_t)r * Ddim + cc]       = make_float2(c[0], c[1]);
            *(float2*)&Oh[(size_t)(r + 8) * Ddim + cc] = make_float2(c[2], c[3]);
        }
    }
}

// ------------------- launch -------------------
extern "C" void kernel_launch(void* const* d_in, const int* in_sizes, int n_in,
                              void* d_out, int out_size)
{
    const float* Q = (const float*)d_in[0];
    const float* K = (const float*)d_in[1];
    const float* V = (const float*)d_in[2];
    float* out = (float*)d_out;
    float* Wt  = out + (size_t)NELEM;  // weights region

    cudaFuncSetAttribute(qk_mma_kernel, cudaFuncAttributeMaxDynamicSharedMemorySize, QK_SMEM);
    cudaFuncSetAttribute(pv_mma_kernel, cudaFuncAttributeMaxDynamicSharedMemorySize, PV_SMEM);

    conv_qk_kernel<<<2 * (NELEM / 4) / 256, 256>>>(Q, K);
    conv_v_kernel<<<dim3(Sdim / 32, Ddim / 32, BHdim), dim3(32, 8)>>>(V);

    qk_mma_kernel<<<dim3(Sdim / 128, Sdim / 128, BHdim), 256, QK_SMEM>>>(Wt);

    reduce_stats_kernel<<<BHdim * Sdim / 256, 256>>>();

    pv_mma_kernel<<<dim3(Sdim / 128, BHdim), 256, PV_SMEM>>>(Wt, out);
}

// round 7
// speedup vs baseline: 1.0563x; 1.0494x over previous
#include <cuda_runtime.h>
#include <cuda_fp16.h>
#include <cstdint>

#define Bdim 2
#define Hdim 16
#define Sdim 2048
#define Ddim 128
#define BHdim (Bdim * Hdim)
#define NELEM 8388608   // BH * S * D

__device__ __half g_Qhi[NELEM];
__device__ __half g_Qlo[NELEM];
__device__ __half g_Khi[NELEM];
__device__ __half g_Klo[NELEM];
__device__ __half g_Vthi[NELEM];   // transposed: [bh][d][s]
__device__ __half g_Vtlo[NELEM];
__device__ float2 g_tileStats[BHdim * Sdim * 16];  // per (row, ktile): (max, expsum)
__device__ float2 g_rowStats[BHdim * Sdim];        // per row: (max, 1/sum)

// ------------------- helpers -------------------
__device__ __forceinline__ void mma_f16(float& d0, float& d1, float& d2, float& d3,
                                        uint32_t a0, uint32_t a1, uint32_t a2, uint32_t a3,
                                        uint32_t b0, uint32_t b1) {
    asm volatile(
        "mma.sync.aligned.m16n8k16.row.col.f32.f16.f16.f32 "
        "{%0,%1,%2,%3}, {%4,%5,%6,%7}, {%8,%9}, {%0,%1,%2,%3};"
        : "+f"(d0), "+f"(d1), "+f"(d2), "+f"(d3)
        : "r"(a0), "r"(a1), "r"(a2), "r"(a3), "r"(b0), "r"(b1));
}
__device__ __forceinline__ void ldsm4(uint32_t& r0, uint32_t& r1, uint32_t& r2, uint32_t& r3,
                                      uint32_t addr) {
    asm volatile("ldmatrix.sync.aligned.m8n8.x4.shared.b16 {%0,%1,%2,%3}, [%4];"
                 : "=r"(r0), "=r"(r1), "=r"(r2), "=r"(r3) : "r"(addr));
}
__device__ __forceinline__ void cpasync16(uint32_t dst, const void* src) {
    asm volatile("cp.async.cg.shared.global [%0], [%1], 16;" :: "r"(dst), "l"(src) : "memory");
}
// fp16 hi/lo split of two floats -> packed half2 words
__device__ __forceinline__ void split2h(float a, float b, uint32_t& hi, uint32_t& lo) {
    __half ha = __float2half_rn(a), hb = __float2half_rn(b);
    float ra = a - __half2float(ha);
    float rb = b - __half2float(hb);
    __half2 hp; hp.x = ha; hp.y = hb;
    __half2 lp = __floats2half2_rn(ra, rb);
    hi = *reinterpret_cast<uint32_t*>(&hp);
    lo = *reinterpret_cast<uint32_t*>(&lp);
}

// ------------------- convert kernels -------------------
__global__ __launch_bounds__(256)
void conv_qk_kernel(const float* __restrict__ Q, const float* __restrict__ K)
{
    const size_t n4 = (size_t)NELEM / 4;
    size_t i = (size_t)blockIdx.x * 256 + threadIdx.x;
    const float sc = 0.08838834764831843f;  // 1/sqrt(128)
    float4 v; __half *hip, *lop; size_t idx;
    if (i < n4) {
        idx = i;
        v = ((const float4*)Q)[idx];
        v.x *= sc; v.y *= sc; v.z *= sc; v.w *= sc;
        hip = g_Qhi; lop = g_Qlo;
    } else {
        idx = i - n4;
        v = ((const float4*)K)[idx];
        hip = g_Khi; lop = g_Klo;
    }
    uint32_t h0, h1, l0, l1;
    split2h(v.x, v.y, h0, l0);
    split2h(v.z, v.w, h1, l1);
    ((uint2*)hip)[idx] = make_uint2(h0, h1);
    ((uint2*)lop)[idx] = make_uint2(l0, l1);
}

__global__ __launch_bounds__(256)
void conv_v_kernel(const float* __restrict__ V)
{
    __shared__ float tile[32][33];
    const int bh = blockIdx.z;
    const int s0 = blockIdx.x * 32;
    const int d0 = blockIdx.y * 32;
    const int tx = threadIdx.x, ty = threadIdx.y;
    const float* Vh = V + (size_t)bh * Sdim * Ddim;

    for (int i = ty; i < 32; i += 8)
        tile[i][tx] = Vh[(size_t)(s0 + i) * Ddim + d0 + tx];
    __syncthreads();

    const size_t base = (size_t)bh * Ddim * Sdim;
    for (int i = ty; i < 32; i += 8) {
        float x = tile[tx][i];   // V[s0+tx][d0+i]
        __half hb = __float2half_rn(x);
        float r = x - __half2float(hb);
        size_t o = base + (size_t)(d0 + i) * Sdim + s0 + tx;
        g_Vthi[o] = hb;
        g_Vtlo[o] = __float2half_rn(r);
    }
}

// ------------------- QK HMMA kernel (fp16 3-term, cp.async, stats epilogue) -------
#define LDA_QK 136
#define QK_PL  (128 * LDA_QK * 2)          // plane bytes: 34816
#define QK_SMEM (4 * QK_PL)                // 139264

__global__ __launch_bounds__(256, 1)
void qk_mma_kernel(float* __restrict__ W)
{
    extern __shared__ __half sm[];
    const int tid = threadIdx.x;
    const int bh = blockIdx.z;
    const int q0 = blockIdx.y * 128;
    const int k0 = blockIdx.x * 128;
    const int ktile = blockIdx.x;

    const size_t qbase = (size_t)bh * Sdim * Ddim + (size_t)q0 * Ddim;
    const size_t kbase = (size_t)bh * Sdim * Ddim + (size_t)k0 * Ddim;
    const uint32_t smb = (uint32_t)__cvta_generic_to_shared(sm);

    const __half* gsrc0 = g_Qhi + qbase;
    const __half* gsrc1 = g_Qlo + qbase;
    const __half* gsrc2 = g_Khi + kbase;
    const __half* gsrc3 = g_Klo + kbase;

#pragma unroll
    for (int ch = 0; ch < 2; ch++) {
#pragma unroll
        for (int j = 0; j < 4; j++) {
            int idx = j * 256 + tid;
            int row = idx >> 3, g = idx & 7;
            uint32_t doff = (uint32_t)((row * LDA_QK + ch * 64 + g * 8) << 1);
            size_t goff = (size_t)row * Ddim + ch * 64 + g * 8;
            cpasync16(smb + 0 * QK_PL + doff, gsrc0 + goff);
            cpasync16(smb + 1 * QK_PL + doff, gsrc1 + goff);
            cpasync16(smb + 2 * QK_PL + doff, gsrc2 + goff);
            cpasync16(smb + 3 * QK_PL + doff, gsrc3 + goff);
        }
        asm volatile("cp.async.commit_group;" ::: "memory");
    }

    const int lane = tid & 31, wid = tid >> 5;
    const int wm = (wid >> 2) * 64, wn = (wid & 3) * 32;
    const int ar = lane >> 2, ac = (lane & 3) * 2;
    const int a_row = wm + ((lane >> 3) & 1) * 8 + (lane & 7);
    const int a_col = (lane >> 4) * 8;
    const int b_row = wn + (lane >> 4) * 8 + (lane & 7);
    const int b_col = ((lane >> 3) & 1) * 8;

    float acc[4][4][4];
#pragma unroll
    for (int mi = 0; mi < 4; mi++)
#pragma unroll
        for (int ni = 0; ni < 4; ni++)
#pragma unroll
            for (int r = 0; r < 4; r++) acc[mi][ni][r] = 0.f;

    asm volatile("cp.async.wait_group 1;" ::: "memory");
    __syncthreads();

#pragma unroll
    for (int ks = 0; ks < 8; ks++) {
        if (ks == 4) {
            asm volatile("cp.async.wait_group 0;" ::: "memory");
            __syncthreads();
        }
        const int kb = ks * 16;
        uint32_t ah[4][4], al[4][4], bh[4][2], bl[4][2];
#pragma unroll
        for (int mi = 0; mi < 4; mi++) {
            uint32_t a = smb + (uint32_t)(((a_row + mi * 16) * LDA_QK + kb + a_col) << 1);
            ldsm4(ah[mi][0], ah[mi][1], ah[mi][2], ah[mi][3], a);
            ldsm4(al[mi][0], al[mi][1], al[mi][2], al[mi][3], a + QK_PL);
        }
#pragma unroll
        for (int np = 0; np < 2; np++) {
            uint32_t b = smb + 2 * QK_PL + (uint32_t)(((b_row + np * 16) * LDA_QK + kb + b_col) << 1);
            uint32_t x0, x1, x2, x3;
            ldsm4(x0, x1, x2, x3, b);
            bh[np * 2][0] = x0; bh[np * 2][1] = x1; bh[np * 2 + 1][0] = x2; bh[np * 2 + 1][1] = x3;
            ldsm4(x0, x1, x2, x3, b + QK_PL);
            bl[np * 2][0] = x0; bl[np * 2][1] = x1; bl[np * 2 + 1][0] = x2; bl[np * 2 + 1][1] = x3;
        }
#pragma unroll
        for (int mi = 0; mi < 4; mi++)
#pragma unroll
            for (int ni = 0; ni < 4; ni++) {
                float* c = acc[mi][ni];
                mma_f16(c[0], c[1], c[2], c[3], ah[mi][0], ah[mi][1], ah[mi][2], ah[mi][3], bh[ni][0], bh[ni][1]);
                mma_f16(c[0], c[1], c[2], c[3], ah[mi][0], ah[mi][1], ah[mi][2], ah[mi][3], bl[ni][0], bl[ni][1]);
                mma_f16(c[0], c[1], c[2], c[3], al[mi][0], al[mi][1], al[mi][2], al[mi][3], bh[ni][0], bh[ni][1]);
            }
    }

    // ---- stats epilogue: per-row (max, expsum) over this 128-col tile ----
    __syncthreads();
    float* sMax = (float*)sm;          // [4][128]
    float* sSum = (float*)sm + 512;    // [4][128]
    const int nw = wid & 3;

#pragma unroll
    for (int mi = 0; mi < 4; mi++)
#pragma unroll
        for (int hh = 0; hh < 2; hh++) {
            float v = acc[mi][0][2 * hh];
#pragma unroll
            for (int ni = 0; ni < 4; ni++) {
                v = fmaxf(v, acc[mi][ni][2 * hh]);
                v = fmaxf(v, acc[mi][ni][2 * hh + 1]);
            }
            v = fmaxf(v, __shfl_xor_sync(0xffffffffu, v, 1));
            v = fmaxf(v, __shfl_xor_sync(0xffffffffu, v, 2));
            if ((lane & 3) == 0)
                sMax[nw * 128 + wm + mi * 16 + hh * 8 + ar] = v;
        }
    __syncthreads();
    if (tid < 128) {
        float m = fmaxf(fmaxf(sMax[tid], sMax[128 + tid]),
                        fmaxf(sMax[256 + tid], sMax[384 + tid]));
        sMax[tid] = m;
    }
    __syncthreads();
#pragma unroll
    for (int mi = 0; mi < 4; mi++)
#pragma unroll
        for (int hh = 0; hh < 2; hh++) {
            float mrow = sMax[wm + mi * 16 + hh * 8 + ar];
            float s = 0.f;
#pragma unroll
            for (int ni = 0; ni < 4; ni++)
                s += __expf(acc[mi][ni][2 * hh] - mrow) + __expf(acc[mi][ni][2 * hh + 1] - mrow);
            s += __shfl_xor_sync(0xffffffffu, s, 1);
            s += __shfl_xor_sync(0xffffffffu, s, 2);
            if ((lane & 3) == 0)
                sSum[nw * 128 + wm + mi * 16 + hh * 8 + ar] = s;
        }
    __syncthreads();
    if (tid < 128) {
        float S = sSum[tid] + sSum[128 + tid] + sSum[256 + tid] + sSum[384 + tid];
        g_tileStats[(size_t)(bh * Sdim + q0 + tid) * 16 + ktile] = make_float2(sMax[tid], S);
    }

    // ---- raw score stores ----
    float* Wh = W + (size_t)bh * Sdim * Sdim;
#pragma unroll
    for (int mi = 0; mi < 4; mi++) {
        const int r = q0 + wm + mi * 16 + ar;
#pragma unroll
        for (int ni = 0; ni < 4; ni++) {
            const int cc = k0 + wn + ni * 8 + ac;
            float* c = acc[mi][ni];
            *(float2*)&Wh[(size_t)r * Sdim + cc]       = make_float2(c[0], c[1]);
            *(float2*)&Wh[(size_t)(r + 8) * Sdim + cc] = make_float2(c[2], c[3]);
        }
    }
}

// ------------------- stats reduce -------------------
__global__ __launch_bounds__(256)
void reduce_stats_kernel()
{
    const int row = blockIdx.x * 256 + threadIdx.x;
    float2 t[16];
    float m = -3.4e38f;
#pragma unroll
    for (int j = 0; j < 16; j++) {
        t[j] = g_tileStats[(size_t)row * 16 + j];
        m = fmaxf(m, t[j].x);
    }
    float S = 0.f;
#pragma unroll
    for (int j = 0; j < 16; j++) S += t[j].y * __expf(t[j].x - m);
    g_rowStats[row] = make_float2(m, 1.f / S);
}

// ------------------- PV HMMA kernel (fp16 2-term: P single, V hi/lo) -------------
#define LDB_PV 40
#define PV_PL   (128 * LDB_PV * 2)          // plane bytes: 10240
#define PV_STG  (3 * PV_PL)                 // stage bytes: 30720 (P, Vhi, Vlo)
#define PV_SMEM (2 * PV_STG)                // 61440

__global__ __launch_bounds__(256, 1)
void pv_mma_kernel(float* __restrict__ W, float* __restrict__ O)
{
    extern __shared__ __half sm[];
    const int tid = threadIdx.x;
    const int q0 = blockIdx.x * 128;
    const int bh = blockIdx.y;

    const int row = tid >> 1, hf = tid & 1;
    float* Wq = W + (size_t)bh * Sdim * Sdim + (size_t)(q0 + row) * Sdim + hf * 16;
    const __half* Vhp = g_Vthi + (size_t)bh * Ddim * Sdim + (size_t)row * Sdim + hf * 16;
    const __half* Vlp = g_Vtlo + (size_t)bh * Ddim * Sdim + (size_t)row * Sdim + hf * 16;

    const float2 st = g_rowStats[bh * Sdim + q0 + row];
    const float rm = st.x, rinv = st.y;

    const int lane = tid & 31, wid = tid >> 5;
    const int wm = (wid >> 2) * 64, wn = (wid & 3) * 32;
    const int ar = lane >> 2, ac = (lane & 3) * 2;

    const uint32_t smb = (uint32_t)__cvta_generic_to_shared(sm);
    const int a_row = wm + ((lane >> 3) & 1) * 8 + (lane & 7);
    const int a_col = (lane >> 4) * 8;
    const int b_row = wn + (lane >> 4) * 8 + (lane & 7);
    const int b_col = ((lane >> 3) & 1) * 8;

    float acc[4][4][4];
#pragma unroll
    for (int mi = 0; mi < 4; mi++)
#pragma unroll
        for (int ni = 0; ni < 4; ni++)
#pragma unroll
            for (int r = 0; r < 4; r++) acc[mi][ni][r] = 0.f;

    float4 fa[4];
    uint4 vh[2], vl[2];
#pragma unroll
    for (int g = 0; g < 4; g++) fa[g] = __ldcs((const float4*)Wq + g);
#pragma unroll
    for (int u = 0; u < 2; u++) { vh[u] = *(const uint4*)(Vhp + u * 8); vl[u] = *(const uint4*)(Vlp + u * 8); }

    const int sbase = row * LDB_PV + hf * 16;

    for (int c = 0; c < 64; c++) {
        const uint32_t stB = (uint32_t)(c & 1) * PV_STG;
        __half* stg = sm + (c & 1) * (PV_STG / 2);

        // exp-normalize -> write normalized W -> P fp16 plane + V planes to smem
        {
            __half* sP   = stg;
            __half* sVhi = stg + 128 * LDB_PV;
            __half* sVlo = stg + 2 * 128 * LDB_PV;
#pragma unroll
            for (int g = 0; g < 4; g++) {
                float4 w4 = fa[g];
                float4 p4 = make_float4(__expf(w4.x - rm) * rinv, __expf(w4.y - rm) * rinv,
                                        __expf(w4.z - rm) * rinv, __expf(w4.w - rm) * rinv);
                __stcs((float4*)(Wq + c * 32) + g, p4);
                __half2 pa = __floats2half2_rn(p4.x, p4.y);
                __half2 pb = __floats2half2_rn(p4.z, p4.w);
                *(uint2*)&sP[sbase + g * 4] =
                    make_uint2(*reinterpret_cast<uint32_t*>(&pa), *reinterpret_cast<uint32_t*>(&pb));
            }
#pragma unroll
            for (int u = 0; u < 2; u++) {
                *(uint4*)&sVhi[sbase + u * 8] = vh[u];
                *(uint4*)&sVlo[sbase + u * 8] = vl[u];
            }
        }
        __syncthreads();

        if (c < 63) {
            const int off = (c + 1) * 32;
#pragma unroll
            for (int g = 0; g < 4; g++) fa[g] = __ldcs((const float4*)(Wq + off) + g);
#pragma unroll
            for (int u = 0; u < 2; u++) {
                vh[u] = *(const uint4*)(Vhp + off + u * 8);
                vl[u] = *(const uint4*)(Vlp + off + u * 8);
            }
        }

#pragma unroll
        for (int ks = 0; ks < 2; ks++) {
            const int kb = ks * 16;
            uint32_t ah[4][4], bh[4][2], bl[4][2];
#pragma unroll
            for (int mi = 0; mi < 4; mi++) {
                uint32_t a = smb + stB + (uint32_t)(((a_row + mi * 16) * LDB_PV + kb + a_col) << 1);
                ldsm4(ah[mi][0], ah[mi][1], ah[mi][2], ah[mi][3], a);
            }
#pragma unroll
            for (int np = 0; np < 2; np++) {
                uint32_t b = smb + stB + PV_PL + (uint32_t)(((b_row + np * 16) * LDB_PV + kb + b_col) << 1);
                uint32_t x0, x1, x2, x3;
                ldsm4(x0, x1, x2, x3, b);
                bh[np * 2][0] = x0; bh[np * 2][1] = x1; bh[np * 2 + 1][0] = x2; bh[np * 2 + 1][1] = x3;
                ldsm4(x0, x1, x2, x3, b + PV_PL);
                bl[np * 2][0] = x0; bl[np * 2][1] = x1; bl[np * 2 + 1][0] = x2; bl[np * 2 + 1][1] = x3;
            }
#pragma unroll
            for (int mi = 0; mi < 4; mi++)
#pragma unroll
                for (int ni = 0; ni < 4; ni++) {
                    float* cc = acc[mi][ni];
                    mma_f16(cc[0], cc[1], cc[2], cc[3], ah[mi][0], ah[mi][1], ah[mi][2], ah[mi][3], bh[ni][0], bh[ni][1]);
                    mma_f16(cc[0], cc[1], cc[2], cc[3], ah[mi][0], ah[mi][1], ah[mi][2], ah[mi][3], bl[ni][0], bl[ni][1]);
                }
        }
    }

    float* Oh = O + (size_t)bh * Sdim * Ddim;
#pragma unroll
    for (int mi = 0; mi < 4; mi++) {
        const int r = q0 + wm + mi * 16 + ar;
#pragma unroll
        for (int ni = 0; ni < 4; ni++) {
            const int cc = wn + ni * 8 + ac;
            float* c = acc[mi][ni];
            *(float2*)&Oh[(size_t)r * Ddim + cc]       = make_float2(c[0], c[1]);
            *(float2*)&Oh[(size_t)(r + 8) * Ddim + cc] = make_float2(c[2], c[3]);
        }
    }
}

// ------------------- launch -------------------
extern "C" void kernel_launch(void* const* d_in, const int* in_sizes, int n_in,
                              void* d_out, int out_size)
{
    const float* Q = (const float*)d_in[0];
    const float* K = (const float*)d_in[1];
    const float* V = (const float*)d_in[2];
    float* out = (float*)d_out;
    float* Wt  = out + (size_t)NELEM;  // weights region

    cudaFuncSetAttribute(qk_mma_kernel, cudaFuncAttributeMaxDynamicSharedMemorySize, QK_SMEM);
    cudaFuncSetAttribute(pv_mma_kernel, cudaFuncAttributeMaxDynamicSharedMemorySize, PV_SMEM);

    conv_qk_kernel<<<2 * (NELEM / 4) / 256, 256>>>(Q, K);
    conv_v_kernel<<<dim3(Sdim / 32, Ddim / 32, BHdim), dim3(32, 8)>>>(V);

    qk_mma_kernel<<<dim3(Sdim / 128, Sdim / 128, BHdim), 256, QK_SMEM>>>(Wt);

    reduce_stats_kernel<<<BHdim * Sdim / 256, 256>>>();

    pv_mma_kernel<<<dim3(Sdim / 128, BHdim), 256, PV_SMEM>>>(Wt, out);
}

// round 8
// speedup vs baseline: 1.2868x; 1.2181x over previous
#include <cuda_runtime.h>
#include <cuda_fp16.h>
#include <cstdint>

#define Bdim 2
#define Hdim 16
#define Sdim 2048
#define Ddim 128
#define BHdim (Bdim * Hdim)
#define NELEM 8388608   // BH * S * D

__device__ __half g_Qh[NELEM];     // scaled Q, single fp16 plane
__device__ __half g_Khi[NELEM];
__device__ __half g_Klo[NELEM];
__device__ __half g_Vthi[NELEM];   // transposed: [bh][d][s]
__device__ __half g_Vtlo[NELEM];
__device__ float2 g_tileStats[BHdim * Sdim * 16];  // per (row, ktile): (max, expsum)
__device__ float2 g_rowStats[BHdim * Sdim];        // per row: (max, 1/sum)

// ------------------- helpers -------------------
__device__ __forceinline__ void mma_f16(float& d0, float& d1, float& d2, float& d3,
                                        uint32_t a0, uint32_t a1, uint32_t a2, uint32_t a3,
                                        uint32_t b0, uint32_t b1) {
    asm volatile(
        "mma.sync.aligned.m16n8k16.row.col.f32.f16.f16.f32 "
        "{%0,%1,%2,%3}, {%4,%5,%6,%7}, {%8,%9}, {%0,%1,%2,%3};"
        : "+f"(d0), "+f"(d1), "+f"(d2), "+f"(d3)
        : "r"(a0), "r"(a1), "r"(a2), "r"(a3), "r"(b0), "r"(b1));
}
__device__ __forceinline__ void ldsm4(uint32_t& r0, uint32_t& r1, uint32_t& r2, uint32_t& r3,
                                      uint32_t addr) {
    asm volatile("ldmatrix.sync.aligned.m8n8.x4.shared.b16 {%0,%1,%2,%3}, [%4];"
                 : "=r"(r0), "=r"(r1), "=r"(r2), "=r"(r3) : "r"(addr));
}
__device__ __forceinline__ void cpasync16(uint32_t dst, const void* src) {
    asm volatile("cp.async.cg.shared.global [%0], [%1], 16;" :: "r"(dst), "l"(src) : "memory");
}
__device__ __forceinline__ void split2h(float a, float b, uint32_t& hi, uint32_t& lo) {
    __half ha = __float2half_rn(a), hb = __float2half_rn(b);
    float ra = a - __half2float(ha);
    float rb = b - __half2float(hb);
    __half2 hp; hp.x = ha; hp.y = hb;
    __half2 lp = __floats2half2_rn(ra, rb);
    hi = *reinterpret_cast<uint32_t*>(&hp);
    lo = *reinterpret_cast<uint32_t*>(&lp);
}

// ------------------- convert kernels -------------------
__global__ __launch_bounds__(256)
void conv_qk_kernel(const float* __restrict__ Q, const float* __restrict__ K)
{
    const size_t n4 = (size_t)NELEM / 4;
    size_t i = (size_t)blockIdx.x * 256 + threadIdx.x;
    const float sc = 0.08838834764831843f;  // 1/sqrt(128)
    if (i < n4) {
        float4 v = ((const float4*)Q)[i];
        __half2 pa = __floats2half2_rn(v.x * sc, v.y * sc);
        __half2 pb = __floats2half2_rn(v.z * sc, v.w * sc);
        ((uint2*)g_Qh)[i] = make_uint2(*reinterpret_cast<uint32_t*>(&pa),
                                       *reinterpret_cast<uint32_t*>(&pb));
    } else {
        size_t idx = i - n4;
        float4 v = ((const float4*)K)[idx];
        uint32_t h0, h1, l0, l1;
        split2h(v.x, v.y, h0, l0);
        split2h(v.z, v.w, h1, l1);
        ((uint2*)g_Khi)[idx] = make_uint2(h0, h1);
        ((uint2*)g_Klo)[idx] = make_uint2(l0, l1);
    }
}

__global__ __launch_bounds__(256)
void conv_v_kernel(const float* __restrict__ V)
{
    __shared__ float tile[32][33];
    const int bh = blockIdx.z;
    const int s0 = blockIdx.x * 32;
    const int d0 = blockIdx.y * 32;
    const int tx = threadIdx.x, ty = threadIdx.y;
    const float* Vh = V + (size_t)bh * Sdim * Ddim;

    for (int i = ty; i < 32; i += 8)
        tile[i][tx] = Vh[(size_t)(s0 + i) * Ddim + d0 + tx];
    __syncthreads();

    const size_t base = (size_t)bh * Ddim * Sdim;
    for (int i = ty; i < 32; i += 8) {
        float x = tile[tx][i];   // V[s0+tx][d0+i]
        __half hb = __float2half_rn(x);
        float r = x - __half2float(hb);
        size_t o = base + (size_t)(d0 + i) * Sdim + s0 + tx;
        g_Vthi[o] = hb;
        g_Vtlo[o] = __float2half_rn(r);
    }
}

// ------------------- QK HMMA kernel (fp16 2-term: Q single, K hi/lo) -------------
#define LDA_QK 136
#define QK_PL  (128 * LDA_QK * 2)          // plane bytes: 34816
#define QK_SMEM (3 * QK_PL)                // 104448 -> 2 CTAs/SM

__global__ __launch_bounds__(256, 2)
void qk_mma_kernel(float* __restrict__ W)
{
    extern __shared__ __half sm[];
    const int tid = threadIdx.x;
    const int bh = blockIdx.z;
    const int q0 = blockIdx.y * 128;
    const int k0 = blockIdx.x * 128;
    const int ktile = blockIdx.x;

    const size_t qbase = (size_t)bh * Sdim * Ddim + (size_t)q0 * Ddim;
    const size_t kbase = (size_t)bh * Sdim * Ddim + (size_t)k0 * Ddim;
    const uint32_t smb = (uint32_t)__cvta_generic_to_shared(sm);

    const __half* gsrc0 = g_Qh  + qbase;
    const __half* gsrc1 = g_Khi + kbase;
    const __half* gsrc2 = g_Klo + kbase;

#pragma unroll
    for (int ch = 0; ch < 2; ch++) {
#pragma unroll
        for (int j = 0; j < 4; j++) {
            int idx = j * 256 + tid;
            int row = idx >> 3, g = idx & 7;
            uint32_t doff = (uint32_t)((row * LDA_QK + ch * 64 + g * 8) << 1);
            size_t goff = (size_t)row * Ddim + ch * 64 + g * 8;
            cpasync16(smb + 0 * QK_PL + doff, gsrc0 + goff);
            cpasync16(smb + 1 * QK_PL + doff, gsrc1 + goff);
            cpasync16(smb + 2 * QK_PL + doff, gsrc2 + goff);
        }
        asm volatile("cp.async.commit_group;" ::: "memory");
    }

    const int lane = tid & 31, wid = tid >> 5;
    const int wm = (wid >> 2) * 64, wn = (wid & 3) * 32;
    const int ar = lane >> 2, ac = (lane & 3) * 2;
    const int a_row = wm + ((lane >> 3) & 1) * 8 + (lane & 7);
    const int a_col = (lane >> 4) * 8;
    const int b_row = wn + (lane >> 4) * 8 + (lane & 7);
    const int b_col = ((lane >> 3) & 1) * 8;

    float acc[4][4][4];
#pragma unroll
    for (int mi = 0; mi < 4; mi++)
#pragma unroll
        for (int ni = 0; ni < 4; ni++)
#pragma unroll
            for (int r = 0; r < 4; r++) acc[mi][ni][r] = 0.f;

    asm volatile("cp.async.wait_group 1;" ::: "memory");
    __syncthreads();

#pragma unroll
    for (int ks = 0; ks < 8; ks++) {
        if (ks == 4) {
            asm volatile("cp.async.wait_group 0;" ::: "memory");
            __syncthreads();
        }
        const int kb = ks * 16;
        uint32_t ah[4][4], bh[4][2], bl[4][2];
#pragma unroll
        for (int mi = 0; mi < 4; mi++) {
            uint32_t a = smb + (uint32_t)(((a_row + mi * 16) * LDA_QK + kb + a_col) << 1);
            ldsm4(ah[mi][0], ah[mi][1], ah[mi][2], ah[mi][3], a);
        }
#pragma unroll
        for (int np = 0; np < 2; np++) {
            uint32_t b = smb + QK_PL + (uint32_t)(((b_row + np * 16) * LDA_QK + kb + b_col) << 1);
            uint32_t x0, x1, x2, x3;
            ldsm4(x0, x1, x2, x3, b);
            bh[np * 2][0] = x0; bh[np * 2][1] = x1; bh[np * 2 + 1][0] = x2; bh[np * 2 + 1][1] = x3;
            ldsm4(x0, x1, x2, x3, b + QK_PL);
            bl[np * 2][0] = x0; bl[np * 2][1] = x1; bl[np * 2 + 1][0] = x2; bl[np * 2 + 1][1] = x3;
        }
#pragma unroll
        for (int mi = 0; mi < 4; mi++)
#pragma unroll
            for (int ni = 0; ni < 4; ni++) {
                float* c = acc[mi][ni];
                mma_f16(c[0], c[1], c[2], c[3], ah[mi][0], ah[mi][1], ah[mi][2], ah[mi][3], bh[ni][0], bh[ni][1]);
                mma_f16(c[0], c[1], c[2], c[3], ah[mi][0], ah[mi][1], ah[mi][2], ah[mi][3], bl[ni][0], bl[ni][1]);
            }
    }

    // ---- stats epilogue: per-row (max, expsum) over this 128-col tile ----
    __syncthreads();
    float* sMax = (float*)sm;          // [4][128]
    float* sSum = (float*)sm + 512;    // [4][128]
    const int nw = wid & 3;

#pragma unroll
    for (int mi = 0; mi < 4; mi++)
#pragma unroll
        for (int hh = 0; hh < 2; hh++) {
            float v = acc[mi][0][2 * hh];
#pragma unroll
            for (int ni = 0; ni < 4; ni++) {
                v = fmaxf(v, acc[mi][ni][2 * hh]);
                v = fmaxf(v, acc[mi][ni][2 * hh + 1]);
            }
            v = fmaxf(v, __shfl_xor_sync(0xffffffffu, v, 1));
            v = fmaxf(v, __shfl_xor_sync(0xffffffffu, v, 2));
            if ((lane & 3) == 0)
                sMax[nw * 128 + wm + mi * 16 + hh * 8 + ar] = v;
        }
    __syncthreads();
    if (tid < 128) {
        float m = fmaxf(fmaxf(sMax[tid], sMax[128 + tid]),
                        fmaxf(sMax[256 + tid], sMax[384 + tid]));
        sMax[tid] = m;
    }
    __syncthreads();
#pragma unroll
    for (int mi = 0; mi < 4; mi++)
#pragma unroll
        for (int hh = 0; hh < 2; hh++) {
            float mrow = sMax[wm + mi * 16 + hh * 8 + ar];
            float s = 0.f;
#pragma unroll
            for (int ni = 0; ni < 4; ni++)
                s += __expf(acc[mi][ni][2 * hh] - mrow) + __expf(acc[mi][ni][2 * hh + 1] - mrow);
            s += __shfl_xor_sync(0xffffffffu, s, 1);
            s += __shfl_xor_sync(0xffffffffu, s, 2);
            if ((lane & 3) == 0)
                sSum[nw * 128 + wm + mi * 16 + hh * 8 + ar] = s;
        }
    __syncthreads();
    if (tid < 128) {
        float S = sSum[tid] + sSum[128 + tid] + sSum[256 + tid] + sSum[384 + tid];
        g_tileStats[(size_t)(bh * Sdim + q0 + tid) * 16 + ktile] = make_float2(sMax[tid], S);
    }

    // ---- raw score stores ----
    float* Wh = W + (size_t)bh * Sdim * Sdim;
#pragma unroll
    for (int mi = 0; mi < 4; mi++) {
        const int r = q0 + wm + mi * 16 + ar;
#pragma unroll
        for (int ni = 0; ni < 4; ni++) {
            const int cc = k0 + wn + ni * 8 + ac;
            float* c = acc[mi][ni];
            *(float2*)&Wh[(size_t)r * Sdim + cc]       = make_float2(c[0], c[1]);
            *(float2*)&Wh[(size_t)(r + 8) * Sdim + cc] = make_float2(c[2], c[3]);
        }
    }
}

// ------------------- stats reduce -------------------
__global__ __launch_bounds__(256)
void reduce_stats_kernel()
{
    const int row = blockIdx.x * 256 + threadIdx.x;
    float2 t[16];
    float m = -3.4e38f;
#pragma unroll
    for (int j = 0; j < 16; j++) {
        t[j] = g_tileStats[(size_t)row * 16 + j];
        m = fmaxf(m, t[j].x);
    }
    float S = 0.f;
#pragma unroll
    for (int j = 0; j < 16; j++) S += t[j].y * __expf(t[j].x - m);
    g_rowStats[row] = make_float2(m, 1.f / S);
}

// ------------------- PV HMMA kernel (fp16 2-term: P single, V hi/lo) -------------
#define LDB_PV 40
#define PV_PL   (128 * LDB_PV * 2)          // plane bytes: 10240
#define PV_STG  (3 * PV_PL)                 // stage bytes: 30720 (P, Vhi, Vlo)
#define PV_SMEM (2 * PV_STG)                // 61440

__global__ __launch_bounds__(256, 1)
void pv_mma_kernel(float* __restrict__ W, float* __restrict__ O)
{
    extern __shared__ __half sm[];
    const int tid = threadIdx.x;
    const int q0 = blockIdx.x * 128;
    const int bh = blockIdx.y;

    const int row = tid >> 1, hf = tid & 1;
    float* Wq = W + (size_t)bh * Sdim * Sdim + (size_t)(q0 + row) * Sdim + hf * 16;
    const __half* Vhp = g_Vthi + (size_t)bh * Ddim * Sdim + (size_t)row * Sdim + hf * 16;
    const __half* Vlp = g_Vtlo + (size_t)bh * Ddim * Sdim + (size_t)row * Sdim + hf * 16;

    const float2 st = g_rowStats[bh * Sdim + q0 + row];
    const float rm = st.x, rinv = st.y;

    const int lane = tid & 31, wid = tid >> 5;
    const int wm = (wid >> 2) * 64, wn = (wid & 3) * 32;
    const int ar = lane >> 2, ac = (lane & 3) * 2;

    const uint32_t smb = (uint32_t)__cvta_generic_to_shared(sm);
    const int a_row = wm + ((lane >> 3) & 1) * 8 + (lane & 7);
    const int a_col = (lane >> 4) * 8;
    const int b_row = wn + (lane >> 4) * 8 + (lane & 7);
    const int b_col = ((lane >> 3) & 1) * 8;

    float acc[4][4][4];
#pragma unroll
    for (int mi = 0; mi < 4; mi++)
#pragma unroll
        for (int ni = 0; ni < 4; ni++)
#pragma unroll
            for (int r = 0; r < 4; r++) acc[mi][ni][r] = 0.f;

    float4 fa[4];
    uint4 vh[2], vl[2];
#pragma unroll
    for (int g = 0; g < 4; g++) fa[g] = __ldcs((const float4*)Wq + g);
#pragma unroll
    for (int u = 0; u < 2; u++) { vh[u] = *(const uint4*)(Vhp + u * 8); vl[u] = *(const uint4*)(Vlp + u * 8); }

    const int sbase = row * LDB_PV + hf * 16;

    for (int c = 0; c < 64; c++) {
        const uint32_t stB = (uint32_t)(c & 1) * PV_STG;
        __half* stg = sm + (c & 1) * (PV_STG / 2);

        {
            __half* sP   = stg;
            __half* sVhi = stg + 128 * LDB_PV;
            __half* sVlo = stg + 2 * 128 * LDB_PV;
#pragma unroll
            for (int g = 0; g < 4; g++) {
                float4 w4 = fa[g];
                float4 p4 = make_float4(__expf(w4.x - rm) * rinv, __expf(w4.y - rm) * rinv,
                                        __expf(w4.z - rm) * rinv, __expf(w4.w - rm) * rinv);
                __stcs((float4*)(Wq + c * 32) + g, p4);
                __half2 pa = __floats2half2_rn(p4.x, p4.y);
                __half2 pb = __floats2half2_rn(p4.z, p4.w);
                *(uint2*)&sP[sbase + g * 4] =
                    make_uint2(*reinterpret_cast<uint32_t*>(&pa), *reinterpret_cast<uint32_t*>(&pb));
            }
#pragma unroll
            for (int u = 0; u < 2; u++) {
                *(uint4*)&sVhi[sbase + u * 8] = vh[u];
                *(uint4*)&sVlo[sbase + u * 8] = vl[u];
            }
        }
        __syncthreads();

        if (c < 63) {
            const int off = (c + 1) * 32;
#pragma unroll
            for (int g = 0; g < 4; g++) fa[g] = __ldcs((const float4*)(Wq + off) + g);
#pragma unroll
            for (int u = 0; u < 2; u++) {
                vh[u] = *(const uint4*)(Vhp + off + u * 8);
                vl[u] = *(const uint4*)(Vlp + off + u * 8);
            }
        }

#pragma unroll
        for (int ks = 0; ks < 2; ks++) {
            const int kb = ks * 16;
            uint32_t ah[4][4], bh[4][2], bl[4][2];
#pragma unroll
            for (int mi = 0; mi < 4; mi++) {
                uint32_t a = smb + stB + (uint32_t)(((a_row + mi * 16) * LDB_PV + kb + a_col) << 1);
                ldsm4(ah[mi][0], ah[mi][1], ah[mi][2], ah[mi][3], a);
            }
#pragma unroll
            for (int np = 0; np < 2; np++) {
                uint32_t b = smb + stB + PV_PL + (uint32_t)(((b_row + np * 16) * LDB_PV + kb + b_col) << 1);
                uint32_t x0, x1, x2, x3;
                ldsm4(x0, x1, x2, x3, b);
                bh[np * 2][0] = x0; bh[np * 2][1] = x1; bh[np * 2 + 1][0] = x2; bh[np * 2 + 1][1] = x3;
                ldsm4(x0, x1, x2, x3, b + PV_PL);
                bl[np * 2][0] = x0; bl[np * 2][1] = x1; bl[np * 2 + 1][0] = x2; bl[np * 2 + 1][1] = x3;
            }
#pragma unroll
            for (int mi = 0; mi < 4; mi++)
#pragma unroll
                for (int ni = 0; ni < 4; ni++) {
                    float* cc = acc[mi][ni];
                    mma_f16(cc[0], cc[1], cc[2], cc[3], ah[mi][0], ah[mi][1], ah[mi][2], ah[mi][3], bh[ni][0], bh[ni][1]);
                    mma_f16(cc[0], cc[1], cc[2], cc[3], ah[mi][0], ah[mi][1], ah[mi][2], ah[mi][3], bl[ni][0], bl[ni][1]);
                }
        }
    }

    float* Oh = O + (size_t)bh * Sdim * Ddim;
#pragma unroll
    for (int mi = 0; mi < 4; mi++) {
        const int r = q0 + wm + mi * 16 + ar;
#pragma unroll
        for (int ni = 0; ni < 4; ni++) {
            const int cc = wn + ni * 8 + ac;
            float* c = acc[mi][ni];
            *(float2*)&Oh[(size_t)r * Ddim + cc]       = make_float2(c[0], c[1]);
            *(float2*)&Oh[(size_t)(r + 8) * Ddim + cc] = make_float2(c[2], c[3]);
        }
    }
}

// ------------------- launch -------------------
extern "C" void kernel_launch(void* const* d_in, const int* in_sizes, int n_in,
                              void* d_out, int out_size)
{
    const float* Q = (const float*)d_in[0];
    const float* K = (const float*)d_in[1];
    const float* V = (const float*)d_in[2];
    float* out = (float*)d_out;
    float* Wt  = out + (size_t)NELEM;  // weights region

    cudaFuncSetAttribute(qk_mma_kernel, cudaFuncAttributeMaxDynamicSharedMemorySize, QK_SMEM);
    cudaFuncSetAttribute(pv_mma_kernel, cudaFuncAttributeMaxDynamicSharedMemorySize, PV_SMEM);

    conv_qk_kernel<<<2 * (NELEM / 4) / 256, 256>>>(Q, K);
    conv_v_kernel<<<dim3(Sdim / 32, Ddim / 32, BHdim), dim3(32, 8)>>>(V);

    qk_mma_kernel<<<dim3(Sdim / 128, Sdim / 128, BHdim), 256, QK_SMEM>>>(Wt);

    reduce_stats_kernel<<<BHdim * Sdim / 256, 256>>>();

    pv_mma_kernel<<<dim3(Sdim / 128, BHdim), 256, PV_SMEM>>>(Wt, out);
}

// round 9
// speedup vs baseline: 1.4849x; 1.1540x over previous
#include <cuda_runtime.h>
#include <cuda_fp16.h>
#include <cstdint>

#define Bdim 2
#define Hdim 16
#define Sdim 2048
#define Ddim 128
#define BHdim (Bdim * Hdim)
#define NELEM 8388608   // BH * S * D

__device__ __half g_Qh[NELEM];     // scaled Q, single fp16 plane
__device__ __half g_Khi[NELEM];
__device__ __half g_Klo[NELEM];
__device__ __half g_Vthi[NELEM];   // transposed: [bh][d][s]
__device__ __half g_Vtlo[NELEM];
__device__ float2 g_tileStats[BHdim * Sdim * 16];  // per (row, ktile): (max, expsum)
__device__ float2 g_rowStats[BHdim * Sdim];        // per row: (max, 1/sum)

// ------------------- helpers -------------------
__device__ __forceinline__ void mma_f16(float& d0, float& d1, float& d2, float& d3,
                                        uint32_t a0, uint32_t a1, uint32_t a2, uint32_t a3,
                                        uint32_t b0, uint32_t b1) {
    asm volatile(
        "mma.sync.aligned.m16n8k16.row.col.f32.f16.f16.f32 "
        "{%0,%1,%2,%3}, {%4,%5,%6,%7}, {%8,%9}, {%0,%1,%2,%3};"
        : "+f"(d0), "+f"(d1), "+f"(d2), "+f"(d3)
        : "r"(a0), "r"(a1), "r"(a2), "r"(a3), "r"(b0), "r"(b1));
}
__device__ __forceinline__ void ldsm4(uint32_t& r0, uint32_t& r1, uint32_t& r2, uint32_t& r3,
                                      uint32_t addr) {
    asm volatile("ldmatrix.sync.aligned.m8n8.x4.shared.b16 {%0,%1,%2,%3}, [%4];"
                 : "=r"(r0), "=r"(r1), "=r"(r2), "=r"(r3) : "r"(addr));
}
__device__ __forceinline__ void cpasync16(uint32_t dst, const void* src) {
    asm volatile("cp.async.cg.shared.global [%0], [%1], 16;" :: "r"(dst), "l"(src) : "memory");
}
__device__ __forceinline__ void split2h(float a, float b, uint32_t& hi, uint32_t& lo) {
    __half ha = __float2half_rn(a), hb = __float2half_rn(b);
    float ra = a - __half2float(ha);
    float rb = b - __half2float(hb);
    __half2 hp; hp.x = ha; hp.y = hb;
    __half2 lp = __floats2half2_rn(ra, rb);
    hi = *reinterpret_cast<uint32_t*>(&hp);
    lo = *reinterpret_cast<uint32_t*>(&lp);
}

// ------------------- convert kernels -------------------
__global__ __launch_bounds__(256)
void conv_qk_kernel(const float* __restrict__ Q, const float* __restrict__ K)
{
    const size_t n4 = (size_t)NELEM / 4;
    size_t i = (size_t)blockIdx.x * 256 + threadIdx.x;
    const float sc = 0.08838834764831843f;  // 1/sqrt(128)
    if (i < n4) {
        float4 v = ((const float4*)Q)[i];
        __half2 pa = __floats2half2_rn(v.x * sc, v.y * sc);
        __half2 pb = __floats2half2_rn(v.z * sc, v.w * sc);
        ((uint2*)g_Qh)[i] = make_uint2(*reinterpret_cast<uint32_t*>(&pa),
                                       *reinterpret_cast<uint32_t*>(&pb));
    } else {
        size_t idx = i - n4;
        float4 v = ((const float4*)K)[idx];
        uint32_t h0, h1, l0, l1;
        split2h(v.x, v.y, h0, l0);
        split2h(v.z, v.w, h1, l1);
        ((uint2*)g_Khi)[idx] = make_uint2(h0, h1);
        ((uint2*)g_Klo)[idx] = make_uint2(l0, l1);
    }
}

__global__ __launch_bounds__(256)
void conv_v_kernel(const float* __restrict__ V)
{
    __shared__ float tile[32][33];
    const int bh = blockIdx.z;
    const int s0 = blockIdx.x * 32;
    const int d0 = blockIdx.y * 32;
    const int tx = threadIdx.x, ty = threadIdx.y;
    const float* Vh = V + (size_t)bh * Sdim * Ddim;

    for (int i = ty; i < 32; i += 8)
        tile[i][tx] = Vh[(size_t)(s0 + i) * Ddim + d0 + tx];
    __syncthreads();

    const size_t base = (size_t)bh * Ddim * Sdim;
    for (int i = ty; i < 32; i += 8) {
        float x = tile[tx][i];   // V[s0+tx][d0+i]
        __half hb = __float2half_rn(x);
        float r = x - __half2float(hb);
        size_t o = base + (size_t)(d0 + i) * Sdim + s0 + tx;
        g_Vthi[o] = hb;
        g_Vtlo[o] = __float2half_rn(r);
    }
}

// ------------------- QK HMMA kernel (fp16 2-term: Q single, K hi/lo) -------------
#define LDA_QK 136
#define QK_PL  (128 * LDA_QK * 2)          // plane bytes: 34816
#define QK_SMEM (3 * QK_PL)                // 104448 -> 2 CTAs/SM

__global__ __launch_bounds__(256, 2)
void qk_mma_kernel(float* __restrict__ W)
{
    extern __shared__ __half sm[];
    const int tid = threadIdx.x;
    const int bh = blockIdx.z;
    const int q0 = blockIdx.y * 128;
    const int k0 = blockIdx.x * 128;
    const int ktile = blockIdx.x;

    const size_t qbase = (size_t)bh * Sdim * Ddim + (size_t)q0 * Ddim;
    const size_t kbase = (size_t)bh * Sdim * Ddim + (size_t)k0 * Ddim;
    const uint32_t smb = (uint32_t)__cvta_generic_to_shared(sm);

    const __half* gsrc0 = g_Qh  + qbase;
    const __half* gsrc1 = g_Khi + kbase;
    const __half* gsrc2 = g_Klo + kbase;

#pragma unroll
    for (int ch = 0; ch < 2; ch++) {
#pragma unroll
        for (int j = 0; j < 4; j++) {
            int idx = j * 256 + tid;
            int row = idx >> 3, g = idx & 7;
            uint32_t doff = (uint32_t)((row * LDA_QK + ch * 64 + g * 8) << 1);
            size_t goff = (size_t)row * Ddim + ch * 64 + g * 8;
            cpasync16(smb + 0 * QK_PL + doff, gsrc0 + goff);
            cpasync16(smb + 1 * QK_PL + doff, gsrc1 + goff);
            cpasync16(smb + 2 * QK_PL + doff, gsrc2 + goff);
        }
        asm volatile("cp.async.commit_group;" ::: "memory");
    }

    const int lane = tid & 31, wid = tid >> 5;
    const int wm = (wid >> 2) * 64, wn = (wid & 3) * 32;
    const int ar = lane >> 2, ac = (lane & 3) * 2;
    const int a_row = wm + ((lane >> 3) & 1) * 8 + (lane & 7);
    const int a_col = (lane >> 4) * 8;
    const int b_row = wn + (lane >> 4) * 8 + (lane & 7);
    const int b_col = ((lane >> 3) & 1) * 8;

    float acc[4][4][4];
#pragma unroll
    for (int mi = 0; mi < 4; mi++)
#pragma unroll
        for (int ni = 0; ni < 4; ni++)
#pragma unroll
            for (int r = 0; r < 4; r++) acc[mi][ni][r] = 0.f;

    asm volatile("cp.async.wait_group 1;" ::: "memory");
    __syncthreads();

#pragma unroll
    for (int ks = 0; ks < 8; ks++) {
        if (ks == 4) {
            asm volatile("cp.async.wait_group 0;" ::: "memory");
            __syncthreads();
        }
        const int kb = ks * 16;
        uint32_t ah[4][4], bh[4][2], bl[4][2];
#pragma unroll
        for (int mi = 0; mi < 4; mi++) {
            uint32_t a = smb + (uint32_t)(((a_row + mi * 16) * LDA_QK + kb + a_col) << 1);
            ldsm4(ah[mi][0], ah[mi][1], ah[mi][2], ah[mi][3], a);
        }
#pragma unroll
        for (int np = 0; np < 2; np++) {
            uint32_t b = smb + QK_PL + (uint32_t)(((b_row + np * 16) * LDA_QK + kb + b_col) << 1);
            uint32_t x0, x1, x2, x3;
            ldsm4(x0, x1, x2, x3, b);
            bh[np * 2][0] = x0; bh[np * 2][1] = x1; bh[np * 2 + 1][0] = x2; bh[np * 2 + 1][1] = x3;
            ldsm4(x0, x1, x2, x3, b + QK_PL);
            bl[np * 2][0] = x0; bl[np * 2][1] = x1; bl[np * 2 + 1][0] = x2; bl[np * 2 + 1][1] = x3;
        }
#pragma unroll
        for (int mi = 0; mi < 4; mi++)
#pragma unroll
            for (int ni = 0; ni < 4; ni++) {
                float* c = acc[mi][ni];
                mma_f16(c[0], c[1], c[2], c[3], ah[mi][0], ah[mi][1], ah[mi][2], ah[mi][3], bh[ni][0], bh[ni][1]);
                mma_f16(c[0], c[1], c[2], c[3], ah[mi][0], ah[mi][1], ah[mi][2], ah[mi][3], bl[ni][0], bl[ni][1]);
            }
    }

    // ---- stats epilogue: per-row (max, expsum) over this 128-col tile ----
    __syncthreads();
    float* sMax = (float*)sm;          // [4][128]
    float* sSum = (float*)sm + 512;    // [4][128]
    const int nw = wid & 3;

#pragma unroll
    for (int mi = 0; mi < 4; mi++)
#pragma unroll
        for (int hh = 0; hh < 2; hh++) {
            float v = acc[mi][0][2 * hh];
#pragma unroll
            for (int ni = 0; ni < 4; ni++) {
                v = fmaxf(v, acc[mi][ni][2 * hh]);
                v = fmaxf(v, acc[mi][ni][2 * hh + 1]);
            }
            v = fmaxf(v, __shfl_xor_sync(0xffffffffu, v, 1));
            v = fmaxf(v, __shfl_xor_sync(0xffffffffu, v, 2));
            if ((lane & 3) == 0)
                sMax[nw * 128 + wm + mi * 16 + hh * 8 + ar] = v;
        }
    __syncthreads();
    if (tid < 128) {
        float m = fmaxf(fmaxf(sMax[tid], sMax[128 + tid]),
                        fmaxf(sMax[256 + tid], sMax[384 + tid]));
        sMax[tid] = m;
    }
    __syncthreads();
#pragma unroll
    for (int mi = 0; mi < 4; mi++)
#pragma unroll
        for (int hh = 0; hh < 2; hh++) {
            float mrow = sMax[wm + mi * 16 + hh * 8 + ar];
            float s = 0.f;
#pragma unroll
            for (int ni = 0; ni < 4; ni++)
                s += __expf(acc[mi][ni][2 * hh] - mrow) + __expf(acc[mi][ni][2 * hh + 1] - mrow);
            s += __shfl_xor_sync(0xffffffffu, s, 1);
            s += __shfl_xor_sync(0xffffffffu, s, 2);
            if ((lane & 3) == 0)
                sSum[nw * 128 + wm + mi * 16 + hh * 8 + ar] = s;
        }
    __syncthreads();
    if (tid < 128) {
        float S = sSum[tid] + sSum[128 + tid] + sSum[256 + tid] + sSum[384 + tid];
        g_tileStats[(size_t)(bh * Sdim + q0 + tid) * 16 + ktile] = make_float2(sMax[tid], S);
    }

    // ---- raw score stores (streaming) ----
    float* Wh = W + (size_t)bh * Sdim * Sdim;
#pragma unroll
    for (int mi = 0; mi < 4; mi++) {
        const int r = q0 + wm + mi * 16 + ar;
#pragma unroll
        for (int ni = 0; ni < 4; ni++) {
            const int cc = k0 + wn + ni * 8 + ac;
            float* c = acc[mi][ni];
            __stcs((float2*)&Wh[(size_t)r * Sdim + cc],       make_float2(c[0], c[1]));
            __stcs((float2*)&Wh[(size_t)(r + 8) * Sdim + cc], make_float2(c[2], c[3]));
        }
    }
}

// ------------------- stats reduce -------------------
__global__ __launch_bounds__(256)
void reduce_stats_kernel()
{
    const int row = blockIdx.x * 256 + threadIdx.x;
    float2 t[16];
    float m = -3.4e38f;
#pragma unroll
    for (int j = 0; j < 16; j++) {
        t[j] = g_tileStats[(size_t)row * 16 + j];
        m = fmaxf(m, t[j].x);
    }
    float S = 0.f;
#pragma unroll
    for (int j = 0; j < 16; j++) S += t[j].y * __expf(t[j].x - m);
    g_rowStats[row] = make_float2(m, 1.f / S);
}

// ------------------- PV HMMA kernel (occ 2: cp.async V, reg-light) ---------------
#define LDB_PV 40
#define PV_PL   (128 * LDB_PV * 2)          // plane bytes: 10240
#define PV_STG  (3 * PV_PL)                 // stage bytes: 30720 (P, Vhi, Vlo)
#define PV_SMEM (2 * PV_STG)                // 61440 -> smem ok for 2 CTAs

__global__ __launch_bounds__(256, 2)
void pv_mma_kernel(float* __restrict__ W, float* __restrict__ O)
{
    extern __shared__ __half sm[];
    const int tid = threadIdx.x;
    const int q0 = blockIdx.x * 128;
    const int bh = blockIdx.y;

    const int row = tid >> 1, hf = tid & 1;
    float* Wq = W + (size_t)bh * Sdim * Sdim + (size_t)(q0 + row) * Sdim + hf * 16;
    const __half* Vhp = g_Vthi + (size_t)bh * Ddim * Sdim + (size_t)row * Sdim + hf * 16;
    const __half* Vlp = g_Vtlo + (size_t)bh * Ddim * Sdim + (size_t)row * Sdim + hf * 16;

    const float2 st = g_rowStats[bh * Sdim + q0 + row];
    const float rm = st.x, rinv = st.y;

    const int lane = tid & 31, wid = tid >> 5;
    const int wm = (wid >> 2) * 64, wn = (wid & 3) * 32;
    const int ar = lane >> 2, ac = (lane & 3) * 2;

    const uint32_t smb = (uint32_t)__cvta_generic_to_shared(sm);
    const int a_row = wm + ((lane >> 3) & 1) * 8 + (lane & 7);
    const int a_col = (lane >> 4) * 8;
    const int b_row = wn + (lane >> 4) * 8 + (lane & 7);
    const int b_col = ((lane >> 3) & 1) * 8;

    const uint32_t vdst = smb + PV_PL + (uint32_t)((row * LDB_PV + hf * 16) << 1);

    float acc[4][4][4];
#pragma unroll
    for (int mi = 0; mi < 4; mi++)
#pragma unroll
        for (int ni = 0; ni < 4; ni++)
#pragma unroll
            for (int r = 0; r < 4; r++) acc[mi][ni][r] = 0.f;

    // prologue: V chunk 0 via cp.async; W chunk 0 via streaming loads
    {
        cpasync16(vdst,               Vhp);
        cpasync16(vdst + 16,          Vhp + 8);
        cpasync16(vdst + PV_PL,       Vlp);
        cpasync16(vdst + PV_PL + 16,  Vlp + 8);
        asm volatile("cp.async.commit_group;" ::: "memory");
    }
    float4 fa[4];
#pragma unroll
    for (int g = 0; g < 4; g++) fa[g] = __ldcs((const float4*)Wq + g);

    const int sbase = row * LDB_PV + hf * 16;

    for (int c = 0; c < 64; c++) {
        const uint32_t stB = (uint32_t)(c & 1) * PV_STG;
        __half* sP = sm + (c & 1) * (PV_STG / 2);

        asm volatile("cp.async.wait_group 0;" ::: "memory");

        // exp-normalize -> write normalized W -> P fp16 plane to smem
#pragma unroll
        for (int g = 0; g < 4; g++) {
            float4 w4 = fa[g];
            float4 p4 = make_float4(__expf(w4.x - rm) * rinv, __expf(w4.y - rm) * rinv,
                                    __expf(w4.z - rm) * rinv, __expf(w4.w - rm) * rinv);
            __stcs((float4*)(Wq + c * 32) + g, p4);
            __half2 pa = __floats2half2_rn(p4.x, p4.y);
            __half2 pb = __floats2half2_rn(p4.z, p4.w);
            *(uint2*)&sP[sbase + g * 4] =
                make_uint2(*reinterpret_cast<uint32_t*>(&pa), *reinterpret_cast<uint32_t*>(&pb));
        }
        __syncthreads();

        if (c < 63) {
            const int off = (c + 1) * 32;
            const uint32_t nstB = (uint32_t)((c + 1) & 1) * PV_STG;
            cpasync16(vdst + nstB,              Vhp + off);
            cpasync16(vdst + nstB + 16,         Vhp + off + 8);
            cpasync16(vdst + nstB + PV_PL,      Vlp + off);
            cpasync16(vdst + nstB + PV_PL + 16, Vlp + off + 8);
            asm volatile("cp.async.commit_group;" ::: "memory");
#pragma unroll
            for (int g = 0; g < 4; g++) fa[g] = __ldcs((const float4*)(Wq + off) + g);
        }

#pragma unroll
        for (int ks = 0; ks < 2; ks++) {
            const int kb = ks * 16;
            uint32_t ah[4][4], bh[4][2], bl[4][2];
#pragma unroll
            for (int mi = 0; mi < 4; mi++) {
                uint32_t a = smb + stB + (uint32_t)(((a_row + mi * 16) * LDB_PV + kb + a_col) << 1);
                ldsm4(ah[mi][0], ah[mi][1], ah[mi][2], ah[mi][3], a);
            }
#pragma unroll
            for (int np = 0; np < 2; np++) {
                uint32_t b = smb + stB + PV_PL + (uint32_t)(((b_row + np * 16) * LDB_PV + kb + b_col) << 1);
                uint32_t x0, x1, x2, x3;
                ldsm4(x0, x1, x2, x3, b);
                bh[np * 2][0] = x0; bh[np * 2][1] = x1; bh[np * 2 + 1][0] = x2; bh[np * 2 + 1][1] = x3;
                ldsm4(x0, x1, x2, x3, b + PV_PL);
                bl[np * 2][0] = x0; bl[np * 2][1] = x1; bl[np * 2 + 1][0] = x2; bl[np * 2 + 1][1] = x3;
            }
#pragma unroll
            for (int mi = 0; mi < 4; mi++)
#pragma unroll
                for (int ni = 0; ni < 4; ni++) {
                    float* cc = acc[mi][ni];
                    mma_f16(cc[0], cc[1], cc[2], cc[3], ah[mi][0], ah[mi][1], ah[mi][2], ah[mi][3], bh[ni][0], bh[ni][1]);
                    mma_f16(cc[0], cc[1], cc[2], cc[3], ah[mi][0], ah[mi][1], ah[mi][2], ah[mi][3], bl[ni][0], bl[ni][1]);
                }
        }
    }

    float* Oh = O + (size_t)bh * Sdim * Ddim;
#pragma unroll
    for (int mi = 0; mi < 4; mi++) {
        const int r = q0 + wm + mi * 16 + ar;
#pragma unroll
        for (int ni = 0; ni < 4; ni++) {
            const int cc = wn + ni * 8 + ac;
            float* c = acc[mi][ni];
            *(float2*)&Oh[(size_t)r * Ddim + cc]       = make_float2(c[0], c[1]);
            *(float2*)&Oh[(size_t)(r + 8) * Ddim + cc] = make_float2(c[2], c[3]);
        }
    }
}

// ------------------- launch -------------------
extern "C" void kernel_launch(void* const* d_in, const int* in_sizes, int n_in,
                              void* d_out, int out_size)
{
    const float* Q = (const float*)d_in[0];
    const float* K = (const float*)d_in[1];
    const float* V = (const float*)d_in[2];
    float* out = (float*)d_out;
    float* Wt  = out + (size_t)NELEM;  // weights region

    cudaFuncSetAttribute(qk_mma_kernel, cudaFuncAttributeMaxDynamicSharedMemorySize, QK_SMEM);
    cudaFuncSetAttribute(pv_mma_kernel, cudaFuncAttributeMaxDynamicSharedMemorySize, PV_SMEM);

    conv_qk_kernel<<<2 * (NELEM / 4) / 256, 256>>>(Q, K);
    conv_v_kernel<<<dim3(Sdim / 32, Ddim / 32, BHdim), dim3(32, 8)>>>(V);

    qk_mma_kernel<<<dim3(Sdim / 128, Sdim / 128, BHdim), 256, QK_SMEM>>>(Wt);

    reduce_stats_kernel<<<BHdim * Sdim / 256, 256>>>();

    pv_mma_kernel<<<dim3(Sdim / 128, BHdim), 256, PV_SMEM>>>(Wt, out);
}